// round 8
// baseline (speedup 1.0000x reference)
#include <cuda_runtime.h>
#include <cuda_bf16.h>
#include <cstdint>

#define NB     256
#define NODES  116
#define FEAT   115
#define HID    128
#define LENN   6670
#define SEG2   13456
#define HC     512
#define STRS   120         // fp32 S row stride (floats)
#define STRE   136         // bf16 matrix row stride (elements)

// smem byte offsets
#define OFF_AH   0                 // A hi [128][136] bf16 (X, later S0+I)  [m][k]
#define OFF_AL   34816             // A lo
#define OFF_BH   69632             // B hi [128][136] bf16 (W, later H') — K-MAJOR [k][n]
#define OFF_BL   104448            // B lo
#define OFF_S    139264            // fp32 S 116x120 (later sMax)
#define OFF_DINV 194944            // 128 floats
#define OFF_BIAS 195456            // 128 floats
#define SMEM_BYTES 195968

__device__ float g_feat[NB * 2 * NODES];   // [256][232]

static __device__ __forceinline__ uint32_t smem_u32(const void* p) {
    uint32_t a;
    asm("{ .reg .u64 t; cvta.to.shared.u64 t, %1; cvt.u32.u64 %0, t; }" : "=r"(a) : "l"(p));
    return a;
}
static __device__ __forceinline__ void ldsm4(uint32_t& r0, uint32_t& r1, uint32_t& r2, uint32_t& r3,
                                             uint32_t a) {
    asm volatile("ldmatrix.sync.aligned.m8n8.x4.shared.b16 {%0,%1,%2,%3}, [%4];"
                 : "=r"(r0), "=r"(r1), "=r"(r2), "=r"(r3) : "r"(a));
}
static __device__ __forceinline__ void ldsm4t(uint32_t& r0, uint32_t& r1, uint32_t& r2, uint32_t& r3,
                                              uint32_t a) {
    asm volatile("ldmatrix.sync.aligned.m8n8.x4.trans.shared.b16 {%0,%1,%2,%3}, [%4];"
                 : "=r"(r0), "=r"(r1), "=r"(r2), "=r"(r3) : "r"(a));
}
static __device__ __forceinline__ void mma_bf16(float4& d,
                                                uint32_t a0, uint32_t a1, uint32_t a2, uint32_t a3,
                                                uint32_t b0, uint32_t b1) {
    asm volatile("mma.sync.aligned.m16n8k16.row.col.f32.bf16.bf16.f32 "
                 "{%0,%1,%2,%3},{%4,%5,%6,%7},{%8,%9},{%0,%1,%2,%3};"
                 : "+f"(d.x), "+f"(d.y), "+f"(d.z), "+f"(d.w)
                 : "r"(a0), "r"(a1), "r"(a2), "r"(a3), "r"(b0), "r"(b1));
}
// split two floats into packed bf16x2 hi and lo words
static __device__ __forceinline__ void split2(float f0, float f1, uint32_t& hi, uint32_t& lo) {
    __nv_bfloat16 h0 = __float2bfloat16(f0), h1 = __float2bfloat16(f1);
    __nv_bfloat16 l0 = __float2bfloat16(f0 - __bfloat162float(h0));
    __nv_bfloat16 l1 = __float2bfloat16(f1 - __bfloat162float(h1));
    hi = (uint32_t)__bfloat16_as_ushort(h0) | ((uint32_t)__bfloat16_as_ushort(h1) << 16);
    lo = (uint32_t)__bfloat16_as_ushort(l0) | ((uint32_t)__bfloat16_as_ushort(l1) << 16);
}

// 128x128x128 GEMM, 3-pass bf16 split; A [m][k] non-trans, B [k][n] trans-ldsm
static __device__ __forceinline__ void gemm128(uint32_t aH, uint32_t aL,
                                               uint32_t bH, uint32_t bL,
                                               float4 (&acc)[2][8],
                                               int wm, int wn, int lane)
{
    const int arow = 32 * wm + (lane & 7) + 8 * ((lane >> 3) & 1);
    const int acol = 8 * (lane >> 4);
    const int bkl  = lane & 15;
    const int bnl  = 64 * wn + 8 * (lane >> 4);

    #pragma unroll 1
    for (int kb = 0; kb < 8; kb++) {
        uint32_t Ah[2][4], Al[2][4];
        #pragma unroll
        for (int mi = 0; mi < 2; mi++) {
            uint32_t offA = (uint32_t)((arow + 16 * mi) * STRE + 16 * kb + acol) * 2;
            ldsm4(Ah[mi][0], Ah[mi][1], Ah[mi][2], Ah[mi][3], aH + offA);
            ldsm4(Al[mi][0], Al[mi][1], Al[mi][2], Al[mi][3], aL + offA);
        }
        #pragma unroll
        for (int j = 0; j < 4; j++) {
            uint32_t offB = (uint32_t)((16 * kb + bkl) * STRE + bnl + 16 * j) * 2;
            uint32_t bh0, bh1, bh2, bh3, bl0, bl1, bl2, bl3;
            ldsm4t(bh0, bh1, bh2, bh3, bH + offB);
            ldsm4t(bl0, bl1, bl2, bl3, bL + offB);
            #pragma unroll
            for (int mi = 0; mi < 2; mi++) {
                mma_bf16(acc[mi][2*j],   Ah[mi][0], Ah[mi][1], Ah[mi][2], Ah[mi][3], bl0, bl1);
                mma_bf16(acc[mi][2*j],   Al[mi][0], Al[mi][1], Al[mi][2], Al[mi][3], bh0, bh1);
                mma_bf16(acc[mi][2*j],   Ah[mi][0], Ah[mi][1], Ah[mi][2], Ah[mi][3], bh0, bh1);
                mma_bf16(acc[mi][2*j+1], Ah[mi][0], Ah[mi][1], Ah[mi][2], Ah[mi][3], bl2, bl3);
                mma_bf16(acc[mi][2*j+1], Al[mi][0], Al[mi][1], Al[mi][2], Al[mi][3], bh2, bh3);
                mma_bf16(acc[mi][2*j+1], Ah[mi][0], Ah[mi][1], Ah[mi][2], Ah[mi][3], bh2, bh3);
            }
        }
    }
}

__global__ void __launch_bounds__(256, 1)
gcn_kernel(const float* __restrict__ x,
           const int*   __restrict__ ei,
           const float* __restrict__ ew,
           const float* __restrict__ W1, const float* __restrict__ b1,
           const float* __restrict__ W2, const float* __restrict__ b2)
{
    extern __shared__ char smc[];
    float* sS    = (float*)(smc + OFF_S);
    float* sDinv = (float*)(smc + OFF_DINV);
    float* sBias = (float*)(smc + OFF_BIAS);

    const int g    = blockIdx.x >> 1;
    const int v    = blockIdx.x & 1;
    const int tid  = threadIdx.x;
    const int wid  = tid >> 5;
    const int lane = tid & 31;
    const int wm   = wid & 3;
    const int wn   = wid >> 2;

    const float* W   = v ? W2 : W1;
    const float* bbp = v ? b2 : b1;
    const float4 z4  = make_float4(0.f, 0.f, 0.f, 0.f);

    // ---- Phase 0: zero S + pad regions only ----
    for (int i = tid; i < 3480; i += 256) ((float4*)(smc + OFF_S))[i] = z4;
    // A pads: rows 0-115, col pairs 58-63 (cols 116-127)
    for (int i = tid; i < 116 * 6; i += 256) {
        int r = i / 6, cp = 58 + (i % 6);
        uint32_t off = (uint32_t)(r * STRE + 2 * cp) * 2;
        *(uint32_t*)(smc + OFF_AH + off) = 0u;
        *(uint32_t*)(smc + OFF_AL + off) = 0u;
    }
    // A rows 116-127 full
    for (int i = tid; i < 12 * 64; i += 256) {
        int r = 116 + (i >> 6), cp = i & 63;
        uint32_t off = (uint32_t)(r * STRE + 2 * cp) * 2;
        *(uint32_t*)(smc + OFF_AH + off) = 0u;
        *(uint32_t*)(smc + OFF_AL + off) = 0u;
    }
    // B rows 115-127 full (W k-pad)
    for (int i = tid; i < 13 * 64; i += 256) {
        int r = 115 + (i >> 6), cp = i & 63;
        uint32_t off = (uint32_t)(r * STRE + 2 * cp) * 2;
        *(uint32_t*)(smc + OFF_BH + off) = 0u;
        *(uint32_t*)(smc + OFF_BL + off) = 0u;
    }
    if (tid < 128) sBias[tid] = bbp[tid];

    // ---- Phase 1: stage X -> A [m][k], W -> B [k][n] (direct); scatter ----
    {
        const float* xg = x + (size_t)(g * (2 * NODES) + v * NODES) * FEAT;
        for (int i = tid; i < NODES * 58; i += 256) {
            int r = i / 58, c2 = i - r * 58;
            float f0 = xg[r * FEAT + 2 * c2];
            float f1 = (c2 < 57) ? xg[r * FEAT + 2 * c2 + 1] : 0.f;
            uint32_t hi, lo;
            split2(f0, f1, hi, lo);
            uint32_t off = (uint32_t)(r * STRE + 2 * c2) * 2;
            *(uint32_t*)(smc + OFF_AH + off) = hi;
            *(uint32_t*)(smc + OFF_AL + off) = lo;
        }
        for (int i = tid; i < (FEAT * HID) / 4; i += 256) {
            int r = i >> 5, c4 = i & 31;
            float4 w = ((const float4*)W)[i];
            uint32_t hi0, lo0, hi1, lo1;
            split2(w.x, w.y, hi0, lo0);
            split2(w.z, w.w, hi1, lo1);
            uint32_t off = (uint32_t)(r * STRE + 4 * c4) * 2;
            *(uint32_t*)(smc + OFF_BH + off)     = hi0;
            *(uint32_t*)(smc + OFF_BH + off + 4) = hi1;
            *(uint32_t*)(smc + OFF_BL + off)     = lo0;
            *(uint32_t*)(smc + OFF_BL + off + 4) = lo1;
        }
        __syncthreads();   // S zero complete before scatter
        const int ebase = g * SEG2 + v * LENN;
        const int off   = g * (2 * NODES) + v * NODES;
        const int*   eis = ei + ebase;
        const int*   eid = ei + (NB * SEG2) + ebase;
        const float* ewp = ew + ebase;
        #pragma unroll 2
        for (int e = tid; e < LENN; e += 256) {
            int s = eis[e] - off;
            int d = eid[e] - off;
            atomicAdd(&sS[d * STRS + s], ewp[e]);
        }
    }
    __syncthreads();

    // ---- Phase 2: dinv[r] = rsqrt(rowsum(S0)+1); rows>=116 -> 1 ----
    for (int r = wid; r < 128; r += 8) {
        float dv = 1.0f;
        if (r < NODES) {
            float s = sS[r * STRS + lane]
                    + sS[r * STRS + 32 + lane]
                    + sS[r * STRS + 64 + lane];
            if (lane < 24) s += sS[r * STRS + 96 + lane];
            #pragma unroll
            for (int o = 16; o; o >>= 1) s += __shfl_xor_sync(0xffffffffu, s, o);
            dv = rsqrtf(s + 1.0f);
        }
        if (lane == 0) sDinv[r] = dv;
    }
    __syncthreads();

    const uint32_t sb = smem_u32(smc);
    const uint32_t aH = sb + OFF_AH, aL = sb + OFF_AL;
    const uint32_t bH = sb + OFF_BH, bL = sb + OFF_BL;
    const int gr = lane >> 2;
    const int t2 = (lane & 3) * 2;

    // ---- Phase 3: GEMM1  H = X @ W ----
    float4 acc[2][8];
    #pragma unroll
    for (int mi = 0; mi < 2; mi++)
        #pragma unroll
        for (int nt = 0; nt < 8; nt++) acc[mi][nt] = z4;
    gemm128(aH, aL, bH, bL, acc, wm, wn, lane);
    __syncthreads();

    // ---- Phase 4: H' = dinv*H -> B [k=node][n=channel] packed; S0+I -> A ----
    #pragma unroll
    for (int mi = 0; mi < 2; mi++) {
        int r0 = 32 * wm + 16 * mi + gr;
        int r1 = r0 + 8;
        float dv0 = sDinv[r0], dv1 = sDinv[r1];
        #pragma unroll
        for (int nt = 0; nt < 8; nt++) {
            int c0 = 64 * wn + 8 * nt + t2;
            float4 a = acc[mi][nt];
            uint32_t hi, lo;
            split2(a.x * dv0, a.y * dv0, hi, lo);
            uint32_t o0 = (uint32_t)(r0 * STRE + c0) * 2;
            *(uint32_t*)(smc + OFF_BH + o0) = hi;
            *(uint32_t*)(smc + OFF_BL + o0) = lo;
            split2(a.z * dv1, a.w * dv1, hi, lo);
            uint32_t o1 = (uint32_t)(r1 * STRE + c0) * 2;
            *(uint32_t*)(smc + OFF_BH + o1) = hi;
            *(uint32_t*)(smc + OFF_BL + o1) = lo;
        }
    }
    for (int i = tid; i < 128 * 64; i += 256) {
        int r = i >> 6, c2 = i & 63;
        int c = 2 * c2;
        float f0 = 0.f, f1 = 0.f;
        if (r < NODES && c < NODES) {
            float2 s = *(float2*)(sS + r * STRS + c);
            f0 = s.x + ((r == c)     ? 1.f : 0.f);
            f1 = s.y + ((r == c + 1) ? 1.f : 0.f);
        }
        uint32_t hi, lo;
        split2(f0, f1, hi, lo);
        uint32_t off = (uint32_t)(r * STRE + c) * 2;
        *(uint32_t*)(smc + OFF_AH + off) = hi;
        *(uint32_t*)(smc + OFF_AL + off) = lo;
    }
    __syncthreads();

    // ---- Phase 5: GEMM2  out = (S0+I) @ H'; epilogue + channel-max ----
    #pragma unroll
    for (int mi = 0; mi < 2; mi++)
        #pragma unroll
        for (int nt = 0; nt < 8; nt++) acc[mi][nt] = z4;
    gemm128(aH, aL, bH, bL, acc, wm, wn, lane);

    float* sMax = sS;   // reuse: [128][2]
    #pragma unroll
    for (int mi = 0; mi < 2; mi++) {
        int r0 = 32 * wm + 16 * mi + gr;
        int r1 = r0 + 8;
        float dv0 = sDinv[r0], dv1 = sDinv[r1];
        float m0 = -3.0e38f, m1 = -3.0e38f;
        #pragma unroll
        for (int nt = 0; nt < 8; nt++) {
            int c0 = 64 * wn + 8 * nt + t2;
            float b0 = sBias[c0], b1 = sBias[c0 + 1];
            float4 a = acc[mi][nt];
            m0 = fmaxf(m0, fmaxf(fmaf(dv0, a.x, b0), fmaf(dv0, a.y, b1)));
            m1 = fmaxf(m1, fmaxf(fmaf(dv1, a.z, b0), fmaf(dv1, a.w, b1)));
        }
        m0 = fmaxf(m0, __shfl_xor_sync(0xffffffffu, m0, 1));
        m0 = fmaxf(m0, __shfl_xor_sync(0xffffffffu, m0, 2));
        m1 = fmaxf(m1, __shfl_xor_sync(0xffffffffu, m1, 1));
        m1 = fmaxf(m1, __shfl_xor_sync(0xffffffffu, m1, 2));
        if ((lane & 3) == 0) {
            sMax[2 * r0 + wn] = m0;
            sMax[2 * r1 + wn] = m1;
        }
    }
    __syncthreads();
    for (int r = tid; r < NODES; r += 256)
        g_feat[g * 232 + v + 2 * r] = fmaxf(sMax[2 * r], sMax[2 * r + 1]);
}

// ---- MLP: 128 CTAs x 2 graphs; K-split halves; float4 W6 loads ----
__global__ void __launch_bounds__(256)
mlp_kernel(const float* __restrict__ W6, const float* __restrict__ b6,
           const float* __restrict__ W7, const float* __restrict__ b7,
           float* __restrict__ out)
{
    __shared__ float  sF[464];
    __shared__ float4 sP[2][2][128];   // [k-half][graph][col-quad]
    __shared__ float  sAcc[2];
    const int tid  = threadIdx.x;
    const int g0   = blockIdx.x * 2;
    const int half = tid >> 7;
    const int cq   = tid & 127;

    for (int i = tid; i < 464; i += 256) sF[i] = g_feat[g0 * 232 + i];
    if (tid < 2) sAcc[tid] = 0.f;
    __syncthreads();

    const float* Wp = W6 + half * 116 * HC;
    const float* f0 = sF + half * 116;
    const float* f1 = sF + 232 + half * 116;

    float4 a0 = make_float4(0.f, 0.f, 0.f, 0.f);
    float4 a1 = make_float4(0.f, 0.f, 0.f, 0.f);
    #pragma unroll 2
    for (int k = 0; k < 116; k += 4) {
        float4 w0 = ((const float4*)(Wp + (k + 0) * HC))[cq];
        float4 w1 = ((const float4*)(Wp + (k + 1) * HC))[cq];
        float4 w2 = ((const float4*)(Wp + (k + 2) * HC))[cq];
        float4 w3 = ((const float4*)(Wp + (k + 3) * HC))[cq];
        float p00 = f0[k], p01 = f0[k+1], p02 = f0[k+2], p03 = f0[k+3];
        float p10 = f1[k], p11 = f1[k+1], p12 = f1[k+2], p13 = f1[k+3];
        a0.x = fmaf(p00, w0.x, a0.x); a0.y = fmaf(p00, w0.y, a0.y);
        a0.z = fmaf(p00, w0.z, a0.z); a0.w = fmaf(p00, w0.w, a0.w);
        a1.x = fmaf(p10, w0.x, a1.x); a1.y = fmaf(p10, w0.y, a1.y);
        a1.z = fmaf(p10, w0.z, a1.z); a1.w = fmaf(p10, w0.w, a1.w);
        a0.x = fmaf(p01, w1.x, a0.x); a0.y = fmaf(p01, w1.y, a0.y);
        a0.z = fmaf(p01, w1.z, a0.z); a0.w = fmaf(p01, w1.w, a0.w);
        a1.x = fmaf(p11, w1.x, a1.x); a1.y = fmaf(p11, w1.y, a1.y);
        a1.z = fmaf(p11, w1.z, a1.z); a1.w = fmaf(p11, w1.w, a1.w);
        a0.x = fmaf(p02, w2.x, a0.x); a0.y = fmaf(p02, w2.y, a0.y);
        a0.z = fmaf(p02, w2.z, a0.z); a0.w = fmaf(p02, w2.w, a0.w);
        a1.x = fmaf(p12, w2.x, a1.x); a1.y = fmaf(p12, w2.y, a1.y);
        a1.z = fmaf(p12, w2.z, a1.z); a1.w = fmaf(p12, w2.w, a1.w);
        a0.x = fmaf(p03, w3.x, a0.x); a0.y = fmaf(p03, w3.y, a0.y);
        a0.z = fmaf(p03, w3.z, a0.z); a0.w = fmaf(p03, w3.w, a0.w);
        a1.x = fmaf(p13, w3.x, a1.x); a1.y = fmaf(p13, w3.y, a1.y);
        a1.z = fmaf(p13, w3.z, a1.z); a1.w = fmaf(p13, w3.w, a1.w);
    }
    sP[half][0][cq] = a0;
    sP[half][1][cq] = a1;
    __syncthreads();

    // combine: thread handles (graph = half, col-quad = cq)
    {
        float4 s0 = sP[0][half][cq];
        float4 s1 = sP[1][half][cq];
        float4 bv = ((const float4*)b6)[cq];
        float4 wv = ((const float4*)W7)[cq];
        float h0 = fmaxf(s0.x + s1.x + bv.x, 0.f);
        float h1 = fmaxf(s0.y + s1.y + bv.y, 0.f);
        float h2 = fmaxf(s0.z + s1.z + bv.z, 0.f);
        float h3 = fmaxf(s0.w + s1.w + bv.w, 0.f);
        float p = fmaf(h0, wv.x, fmaf(h1, wv.y, fmaf(h2, wv.z, h3 * wv.w)));
        #pragma unroll
        for (int o = 16; o; o >>= 1) p += __shfl_xor_sync(0xffffffffu, p, o);
        if ((tid & 31) == 0) atomicAdd(&sAcc[half], p);
    }
    __syncthreads();
    if (tid < 2) out[g0 + tid] = sAcc[tid] + b7[0];
}

extern "C" void kernel_launch(void* const* d_in, const int* in_sizes, int n_in,
                              void* d_out, int out_size)
{
    const float* x  = (const float*)d_in[0];
    const int*   ei = (const int*)  d_in[1];
    const float* ew = (const float*)d_in[2];
    // d_in[3] = batch (unused)
    const float* W1 = (const float*)d_in[4];
    const float* b1 = (const float*)d_in[5];
    const float* W2 = (const float*)d_in[6];
    const float* b2 = (const float*)d_in[7];
    const float* W6 = (const float*)d_in[8];
    const float* b6 = (const float*)d_in[9];
    const float* W7 = (const float*)d_in[10];
    const float* b7 = (const float*)d_in[11];

    cudaFuncSetAttribute(gcn_kernel, cudaFuncAttributeMaxDynamicSharedMemorySize, SMEM_BYTES);

    gcn_kernel<<<2 * NB, 256, SMEM_BYTES>>>(x, ei, ew, W1, b1, W2, b2);
    mlp_kernel<<<NB / 2, 256>>>(W6, b6, W7, b7, (float*)d_out);
}

// round 9
// speedup vs baseline: 1.1982x; 1.1982x over previous
#include <cuda_runtime.h>
#include <cuda_bf16.h>
#include <cstdint>

#define NB     256
#define NODES  116
#define FEAT   115
#define HID    128
#define LENN   6670
#define SEG2   13456
#define HC     512
#define STRS   120         // fp32 S row stride (floats)
#define STRE   136         // bf16 matrix row stride (elements)

// smem byte offsets
#define OFF_AH   0                 // A hi [128][136] bf16 (X, later S0+I)  [m][k]
#define OFF_AL   34816             // A lo
#define OFF_BH   69632             // B hi [128][136] bf16 (W, later H') — K-MAJOR [k][n]
#define OFF_BL   104448            // B lo
#define OFF_S    139264            // fp32 S 116x120 (later sMax)
#define OFF_DINV 194944            // 128 floats
#define OFF_BIAS 195456            // 128 floats
#define SMEM_BYTES 195968

__device__ float g_feat[NB * 2 * NODES];   // [256][232]

static __device__ __forceinline__ uint32_t smem_u32(const void* p) {
    uint32_t a;
    asm("{ .reg .u64 t; cvta.to.shared.u64 t, %1; cvt.u32.u64 %0, t; }" : "=r"(a) : "l"(p));
    return a;
}
static __device__ __forceinline__ void ldsm4(uint32_t& r0, uint32_t& r1, uint32_t& r2, uint32_t& r3,
                                             uint32_t a) {
    asm volatile("ldmatrix.sync.aligned.m8n8.x4.shared.b16 {%0,%1,%2,%3}, [%4];"
                 : "=r"(r0), "=r"(r1), "=r"(r2), "=r"(r3) : "r"(a));
}
static __device__ __forceinline__ void ldsm4t(uint32_t& r0, uint32_t& r1, uint32_t& r2, uint32_t& r3,
                                              uint32_t a) {
    asm volatile("ldmatrix.sync.aligned.m8n8.x4.trans.shared.b16 {%0,%1,%2,%3}, [%4];"
                 : "=r"(r0), "=r"(r1), "=r"(r2), "=r"(r3) : "r"(a));
}
static __device__ __forceinline__ void mma_bf16(float4& d,
                                                uint32_t a0, uint32_t a1, uint32_t a2, uint32_t a3,
                                                uint32_t b0, uint32_t b1) {
    asm volatile("mma.sync.aligned.m16n8k16.row.col.f32.bf16.bf16.f32 "
                 "{%0,%1,%2,%3},{%4,%5,%6,%7},{%8,%9},{%0,%1,%2,%3};"
                 : "+f"(d.x), "+f"(d.y), "+f"(d.z), "+f"(d.w)
                 : "r"(a0), "r"(a1), "r"(a2), "r"(a3), "r"(b0), "r"(b1));
}
static __device__ __forceinline__ void split2(float f0, float f1, uint32_t& hi, uint32_t& lo) {
    __nv_bfloat16 h0 = __float2bfloat16(f0), h1 = __float2bfloat16(f1);
    __nv_bfloat16 l0 = __float2bfloat16(f0 - __bfloat162float(h0));
    __nv_bfloat16 l1 = __float2bfloat16(f1 - __bfloat162float(h1));
    hi = (uint32_t)__bfloat16_as_ushort(h0) | ((uint32_t)__bfloat16_as_ushort(h1) << 16);
    lo = (uint32_t)__bfloat16_as_ushort(l0) | ((uint32_t)__bfloat16_as_ushort(l1) << 16);
}

// 128x128x128 GEMM, 3-pass bf16 split; A [m][k] non-trans, B [k][n] trans-ldsm
static __device__ __forceinline__ void gemm128(uint32_t aH, uint32_t aL,
                                               uint32_t bH, uint32_t bL,
                                               float4 (&acc)[2][8],
                                               int wm, int wn, int lane)
{
    const int arow = 32 * wm + (lane & 7) + 8 * ((lane >> 3) & 1);
    const int acol = 8 * (lane >> 4);
    const int bkl  = lane & 15;
    const int bnl  = 64 * wn + 8 * (lane >> 4);

    #pragma unroll 1
    for (int kb = 0; kb < 8; kb++) {
        uint32_t Ah[2][4], Al[2][4];
        #pragma unroll
        for (int mi = 0; mi < 2; mi++) {
            uint32_t offA = (uint32_t)((arow + 16 * mi) * STRE + 16 * kb + acol) * 2;
            ldsm4(Ah[mi][0], Ah[mi][1], Ah[mi][2], Ah[mi][3], aH + offA);
            ldsm4(Al[mi][0], Al[mi][1], Al[mi][2], Al[mi][3], aL + offA);
        }
        #pragma unroll
        for (int j = 0; j < 4; j++) {
            uint32_t offB = (uint32_t)((16 * kb + bkl) * STRE + bnl + 16 * j) * 2;
            uint32_t bh0, bh1, bh2, bh3, bl0, bl1, bl2, bl3;
            ldsm4t(bh0, bh1, bh2, bh3, bH + offB);
            ldsm4t(bl0, bl1, bl2, bl3, bL + offB);
            #pragma unroll
            for (int mi = 0; mi < 2; mi++) {
                mma_bf16(acc[mi][2*j],   Ah[mi][0], Ah[mi][1], Ah[mi][2], Ah[mi][3], bl0, bl1);
                mma_bf16(acc[mi][2*j],   Al[mi][0], Al[mi][1], Al[mi][2], Al[mi][3], bh0, bh1);
                mma_bf16(acc[mi][2*j],   Ah[mi][0], Ah[mi][1], Ah[mi][2], Ah[mi][3], bh0, bh1);
                mma_bf16(acc[mi][2*j+1], Ah[mi][0], Ah[mi][1], Ah[mi][2], Ah[mi][3], bl2, bl3);
                mma_bf16(acc[mi][2*j+1], Al[mi][0], Al[mi][1], Al[mi][2], Al[mi][3], bh2, bh3);
                mma_bf16(acc[mi][2*j+1], Ah[mi][0], Ah[mi][1], Ah[mi][2], Ah[mi][3], bh2, bh3);
            }
        }
    }
}

__global__ void __launch_bounds__(256, 1)
gcn_kernel(const float* __restrict__ x,
           const int*   __restrict__ ei,
           const float* __restrict__ ew,
           const float* __restrict__ W1, const float* __restrict__ b1,
           const float* __restrict__ W2, const float* __restrict__ b2)
{
    extern __shared__ char smc[];
    float* sS    = (float*)(smc + OFF_S);
    float* sDinv = (float*)(smc + OFF_DINV);
    float* sBias = (float*)(smc + OFF_BIAS);

    const int g    = blockIdx.x >> 1;
    const int v    = blockIdx.x & 1;
    const int tid  = threadIdx.x;
    const int wid  = tid >> 5;
    const int lane = tid & 31;
    const int wm   = wid & 3;
    const int wn   = wid >> 2;

    const float* W   = v ? W2 : W1;
    const float* bbp = v ? b2 : b1;
    const float4 z4  = make_float4(0.f, 0.f, 0.f, 0.f);

    // ---- Phase 0: zero S + pad regions only ----
    for (int i = tid; i < 3480; i += 256) ((float4*)(smc + OFF_S))[i] = z4;
    for (int i = tid; i < 116 * 6; i += 256) {           // A cols 116-127, rows 0-115
        int r = i / 6, cp = 58 + (i % 6);
        uint32_t off = (uint32_t)(r * STRE + 2 * cp) * 2;
        *(uint32_t*)(smc + OFF_AH + off) = 0u;
        *(uint32_t*)(smc + OFF_AL + off) = 0u;
    }
    for (int i = tid; i < 12 * 64; i += 256) {           // A rows 116-127
        int r = 116 + (i >> 6), cp = i & 63;
        uint32_t off = (uint32_t)(r * STRE + 2 * cp) * 2;
        *(uint32_t*)(smc + OFF_AH + off) = 0u;
        *(uint32_t*)(smc + OFF_AL + off) = 0u;
    }
    for (int i = tid; i < 13 * 64; i += 256) {           // B rows 115-127
        int r = 115 + (i >> 6), cp = i & 63;
        uint32_t off = (uint32_t)(r * STRE + 2 * cp) * 2;
        *(uint32_t*)(smc + OFF_BH + off) = 0u;
        *(uint32_t*)(smc + OFF_BL + off) = 0u;
    }
    if (tid < 128) sBias[tid] = bbp[tid];

    // ---- Phase 1: stage X -> A [m][k], W -> B [k][n]; scatter (8x batched) ----
    {
        const float* xg = x + (size_t)(g * (2 * NODES) + v * NODES) * FEAT;
        for (int i = tid; i < NODES * 58; i += 256) {
            int r = i / 58, c2 = i - r * 58;
            float f0 = xg[r * FEAT + 2 * c2];
            float f1 = (c2 < 57) ? xg[r * FEAT + 2 * c2 + 1] : 0.f;
            uint32_t hi, lo;
            split2(f0, f1, hi, lo);
            uint32_t off = (uint32_t)(r * STRE + 2 * c2) * 2;
            *(uint32_t*)(smc + OFF_AH + off) = hi;
            *(uint32_t*)(smc + OFF_AL + off) = lo;
        }
        for (int i = tid; i < (FEAT * HID) / 4; i += 256) {
            int r = i >> 5, c4 = i & 31;
            float4 w = ((const float4*)W)[i];
            uint32_t hi0, lo0, hi1, lo1;
            split2(w.x, w.y, hi0, lo0);
            split2(w.z, w.w, hi1, lo1);
            uint32_t off = (uint32_t)(r * STRE + 4 * c4) * 2;
            *(uint32_t*)(smc + OFF_BH + off)     = hi0;
            *(uint32_t*)(smc + OFF_BH + off + 4) = hi1;
            *(uint32_t*)(smc + OFF_BL + off)     = lo0;
            *(uint32_t*)(smc + OFF_BL + off + 4) = lo1;
        }
        __syncthreads();   // S zero complete before scatter
        const int ebase = g * SEG2 + v * LENN;
        const int off   = g * (2 * NODES) + v * NODES;
        const int*   eis = ei + ebase;
        const int*   eid = ei + (NB * SEG2) + ebase;
        const float* ewp = ew + ebase;
        // 8-way batched scatter: 3 super-batches of 2048 then tail
        for (int e0 = tid; e0 < 6144; e0 += 2048) {
            int   s[8]; int d[8]; float w8[8];
            #pragma unroll
            for (int j = 0; j < 8; j++) s[j]  = eis[e0 + 256 * j];
            #pragma unroll
            for (int j = 0; j < 8; j++) d[j]  = eid[e0 + 256 * j];
            #pragma unroll
            for (int j = 0; j < 8; j++) w8[j] = ewp[e0 + 256 * j];
            #pragma unroll
            for (int j = 0; j < 8; j++)
                atomicAdd(&sS[(d[j] - off) * STRS + (s[j] - off)], w8[j]);
        }
        for (int e = 6144 + tid; e < LENN; e += 256) {
            int s = eis[e] - off;
            int d = eid[e] - off;
            atomicAdd(&sS[d * STRS + s], ewp[e]);
        }
    }
    __syncthreads();

    // ---- Phase 2: dinv[r] = rsqrt(rowsum(S0)+1); rows>=116 -> 1 ----
    for (int r = wid; r < 128; r += 8) {
        float dv = 1.0f;
        if (r < NODES) {
            float s = sS[r * STRS + lane]
                    + sS[r * STRS + 32 + lane]
                    + sS[r * STRS + 64 + lane];
            if (lane < 24) s += sS[r * STRS + 96 + lane];
            #pragma unroll
            for (int o = 16; o; o >>= 1) s += __shfl_xor_sync(0xffffffffu, s, o);
            dv = rsqrtf(s + 1.0f);
        }
        if (lane == 0) sDinv[r] = dv;
    }
    __syncthreads();

    const uint32_t sb = smem_u32(smc);
    const uint32_t aH = sb + OFF_AH, aL = sb + OFF_AL;
    const uint32_t bH = sb + OFF_BH, bL = sb + OFF_BL;
    const int gr = lane >> 2;
    const int t2 = (lane & 3) * 2;

    // ---- Phase 3: GEMM1  H = X @ W ----
    float4 acc[2][8];
    #pragma unroll
    for (int mi = 0; mi < 2; mi++)
        #pragma unroll
        for (int nt = 0; nt < 8; nt++) acc[mi][nt] = z4;
    gemm128(aH, aL, bH, bL, acc, wm, wn, lane);
    __syncthreads();

    // ---- Phase 4: H' = dinv*H -> B [k=node][n=channel]; S0+I -> A ----
    #pragma unroll
    for (int mi = 0; mi < 2; mi++) {
        int r0 = 32 * wm + 16 * mi + gr;
        int r1 = r0 + 8;
        float dv0 = sDinv[r0], dv1 = sDinv[r1];
        #pragma unroll
        for (int nt = 0; nt < 8; nt++) {
            int c0 = 64 * wn + 8 * nt + t2;
            float4 a = acc[mi][nt];
            uint32_t hi, lo;
            split2(a.x * dv0, a.y * dv0, hi, lo);
            uint32_t o0 = (uint32_t)(r0 * STRE + c0) * 2;
            *(uint32_t*)(smc + OFF_BH + o0) = hi;
            *(uint32_t*)(smc + OFF_BL + o0) = lo;
            split2(a.z * dv1, a.w * dv1, hi, lo);
            uint32_t o1 = (uint32_t)(r1 * STRE + c0) * 2;
            *(uint32_t*)(smc + OFF_BH + o1) = hi;
            *(uint32_t*)(smc + OFF_BL + o1) = lo;
        }
    }
    for (int i = tid; i < 128 * 64; i += 256) {
        int r = i >> 6, c2 = i & 63;
        int c = 2 * c2;
        float f0 = 0.f, f1 = 0.f;
        if (r < NODES && c < NODES) {
            float2 s = *(float2*)(sS + r * STRS + c);
            f0 = s.x + ((r == c)     ? 1.f : 0.f);
            f1 = s.y + ((r == c + 1) ? 1.f : 0.f);
        }
        uint32_t hi, lo;
        split2(f0, f1, hi, lo);
        uint32_t off = (uint32_t)(r * STRE + c) * 2;
        *(uint32_t*)(smc + OFF_AH + off) = hi;
        *(uint32_t*)(smc + OFF_AL + off) = lo;
    }
    __syncthreads();

    // ---- Phase 5: GEMM2  out = (S0+I) @ H'; epilogue + channel-max ----
    #pragma unroll
    for (int mi = 0; mi < 2; mi++)
        #pragma unroll
        for (int nt = 0; nt < 8; nt++) acc[mi][nt] = z4;
    gemm128(aH, aL, bH, bL, acc, wm, wn, lane);

    float* sMax = sS;   // reuse: [128][2]
    #pragma unroll
    for (int mi = 0; mi < 2; mi++) {
        int r0 = 32 * wm + 16 * mi + gr;
        int r1 = r0 + 8;
        float dv0 = sDinv[r0], dv1 = sDinv[r1];
        float m0 = -3.0e38f, m1 = -3.0e38f;
        #pragma unroll
        for (int nt = 0; nt < 8; nt++) {
            int c0 = 64 * wn + 8 * nt + t2;
            float b0 = sBias[c0], b1 = sBias[c0 + 1];
            float4 a = acc[mi][nt];
            m0 = fmaxf(m0, fmaxf(fmaf(dv0, a.x, b0), fmaf(dv0, a.y, b1)));
            m1 = fmaxf(m1, fmaxf(fmaf(dv1, a.z, b0), fmaf(dv1, a.w, b1)));
        }
        m0 = fmaxf(m0, __shfl_xor_sync(0xffffffffu, m0, 1));
        m0 = fmaxf(m0, __shfl_xor_sync(0xffffffffu, m0, 2));
        m1 = fmaxf(m1, __shfl_xor_sync(0xffffffffu, m1, 1));
        m1 = fmaxf(m1, __shfl_xor_sync(0xffffffffu, m1, 2));
        if ((lane & 3) == 0) {
            sMax[2 * r0 + wn] = m0;
            sMax[2 * r1 + wn] = m1;
        }
    }
    __syncthreads();
    for (int r = tid; r < NODES; r += 256)
        g_feat[g * 232 + v + 2 * r] = fmaxf(sMax[2 * r], sMax[2 * r + 1]);
}

// ---- MLP (R7 proven version): 256 CTAs x 1 graph; K-split halves ----
__global__ void __launch_bounds__(256, 1)
mlp_kernel(const float* __restrict__ W6, const float* __restrict__ b6,
           const float* __restrict__ W7, const float* __restrict__ b7,
           float* __restrict__ out)
{
    __shared__ float  sF[232];
    __shared__ float4 sP[2][128];
    __shared__ float  sAcc;
    const int tid  = threadIdx.x;
    const int g    = blockIdx.x;
    const int half = tid >> 7;
    const int cq   = tid & 127;

    for (int i = tid; i < 232; i += 256) sF[i] = g_feat[g * 232 + i];
    if (tid == 0) sAcc = 0.f;
    __syncthreads();

    const float* Wp = W6 + half * 116 * HC;
    const float* fp = sF + half * 116;

    float4 acc = make_float4(0.f, 0.f, 0.f, 0.f);
    #pragma unroll 2
    for (int k = 0; k < 116; k += 4) {
        float4 w0 = ((const float4*)(Wp + (k + 0) * HC))[cq];
        float4 w1 = ((const float4*)(Wp + (k + 1) * HC))[cq];
        float4 w2 = ((const float4*)(Wp + (k + 2) * HC))[cq];
        float4 w3 = ((const float4*)(Wp + (k + 3) * HC))[cq];
        float p0 = fp[k], p1 = fp[k + 1], p2 = fp[k + 2], p3 = fp[k + 3];
        acc.x = fmaf(p0, w0.x, acc.x); acc.y = fmaf(p0, w0.y, acc.y);
        acc.z = fmaf(p0, w0.z, acc.z); acc.w = fmaf(p0, w0.w, acc.w);
        acc.x = fmaf(p1, w1.x, acc.x); acc.y = fmaf(p1, w1.y, acc.y);
        acc.z = fmaf(p1, w1.z, acc.z); acc.w = fmaf(p1, w1.w, acc.w);
        acc.x = fmaf(p2, w2.x, acc.x); acc.y = fmaf(p2, w2.y, acc.y);
        acc.z = fmaf(p2, w2.z, acc.z); acc.w = fmaf(p2, w2.w, acc.w);
        acc.x = fmaf(p3, w3.x, acc.x); acc.y = fmaf(p3, w3.y, acc.y);
        acc.z = fmaf(p3, w3.z, acc.z); acc.w = fmaf(p3, w3.w, acc.w);
    }
    sP[half][cq] = acc;
    __syncthreads();

    if (tid < 128) {
        float4 s0 = sP[0][tid];
        float4 s1 = sP[1][tid];
        float4 bv = ((const float4*)b6)[tid];
        float4 wv = ((const float4*)W7)[tid];
        float h0 = fmaxf(s0.x + s1.x + bv.x, 0.f);
        float h1 = fmaxf(s0.y + s1.y + bv.y, 0.f);
        float h2 = fmaxf(s0.z + s1.z + bv.z, 0.f);
        float h3 = fmaxf(s0.w + s1.w + bv.w, 0.f);
        float p = fmaf(h0, wv.x, fmaf(h1, wv.y, fmaf(h2, wv.z, h3 * wv.w)));
        #pragma unroll
        for (int o = 16; o; o >>= 1) p += __shfl_xor_sync(0xffffffffu, p, o);
        if ((tid & 31) == 0) atomicAdd(&sAcc, p);
    }
    __syncthreads();
    if (tid == 0) out[g] = sAcc + b7[0];
}

extern "C" void kernel_launch(void* const* d_in, const int* in_sizes, int n_in,
                              void* d_out, int out_size)
{
    const float* x  = (const float*)d_in[0];
    const int*   ei = (const int*)  d_in[1];
    const float* ew = (const float*)d_in[2];
    // d_in[3] = batch (unused)
    const float* W1 = (const float*)d_in[4];
    const float* b1 = (const float*)d_in[5];
    const float* W2 = (const float*)d_in[6];
    const float* b2 = (const float*)d_in[7];
    const float* W6 = (const float*)d_in[8];
    const float* b6 = (const float*)d_in[9];
    const float* W7 = (const float*)d_in[10];
    const float* b7 = (const float*)d_in[11];

    cudaFuncSetAttribute(gcn_kernel, cudaFuncAttributeMaxDynamicSharedMemorySize, SMEM_BYTES);

    gcn_kernel<<<2 * NB, 256, SMEM_BYTES>>>(x, ei, ew, W1, b1, W2, b2);
    mlp_kernel<<<NB, 256>>>(W6, b6, W7, b7, (float*)d_out);
}

// round 10
// speedup vs baseline: 1.2517x; 1.0446x over previous
#include <cuda_runtime.h>
#include <cuda_bf16.h>
#include <cstdint>

#define NB     256
#define NODES  116
#define FEAT   115
#define HID    128
#define LENN   6670
#define SEG2   13456
#define HC     512
#define STRS   120         // fp32 S row stride (floats)
#define STRE   136         // bf16 matrix row stride (elements)

// smem byte offsets
#define OFF_AH   0                 // A hi [128][136] bf16 (X, later S0+I)  [m][k]
#define OFF_AL   34816             // A lo
#define OFF_BH   69632             // B hi [128][136] bf16 (W, later H') — K-MAJOR [k][n]
#define OFF_BL   104448            // B lo
#define OFF_S    139264            // fp32 S 116x120 (later sMax)
#define OFF_DINV 194944            // 128 floats
#define OFF_BIAS 195456            // 128 floats
#define SMEM_BYTES 195968

__device__ float g_featT[232 * NB];   // TRANSPOSED: featT[k][g], k = 2*node + view

static __device__ __forceinline__ uint32_t smem_u32(const void* p) {
    uint32_t a;
    asm("{ .reg .u64 t; cvta.to.shared.u64 t, %1; cvt.u32.u64 %0, t; }" : "=r"(a) : "l"(p));
    return a;
}
static __device__ __forceinline__ void ldsm4(uint32_t& r0, uint32_t& r1, uint32_t& r2, uint32_t& r3,
                                             uint32_t a) {
    asm volatile("ldmatrix.sync.aligned.m8n8.x4.shared.b16 {%0,%1,%2,%3}, [%4];"
                 : "=r"(r0), "=r"(r1), "=r"(r2), "=r"(r3) : "r"(a));
}
static __device__ __forceinline__ void ldsm4t(uint32_t& r0, uint32_t& r1, uint32_t& r2, uint32_t& r3,
                                              uint32_t a) {
    asm volatile("ldmatrix.sync.aligned.m8n8.x4.trans.shared.b16 {%0,%1,%2,%3}, [%4];"
                 : "=r"(r0), "=r"(r1), "=r"(r2), "=r"(r3) : "r"(a));
}
static __device__ __forceinline__ void mma_bf16(float4& d,
                                                uint32_t a0, uint32_t a1, uint32_t a2, uint32_t a3,
                                                uint32_t b0, uint32_t b1) {
    asm volatile("mma.sync.aligned.m16n8k16.row.col.f32.bf16.bf16.f32 "
                 "{%0,%1,%2,%3},{%4,%5,%6,%7},{%8,%9},{%0,%1,%2,%3};"
                 : "+f"(d.x), "+f"(d.y), "+f"(d.z), "+f"(d.w)
                 : "r"(a0), "r"(a1), "r"(a2), "r"(a3), "r"(b0), "r"(b1));
}
// packed split: one cvt.bf16x2 for hi pair, exact hi recovery by masks, one for lo pair
static __device__ __forceinline__ void split2(float f0, float f1, uint32_t& hi, uint32_t& lo) {
    asm("cvt.rn.bf16x2.f32 %0, %1, %2;" : "=r"(hi) : "f"(f1), "f"(f0));
    float h0 = __uint_as_float(hi << 16);
    float h1 = __uint_as_float(hi & 0xFFFF0000u);
    float l0 = f0 - h0;
    float l1 = f1 - h1;
    asm("cvt.rn.bf16x2.f32 %0, %1, %2;" : "=r"(lo) : "f"(l1), "f"(l0));
}

// 128x128x128 GEMM, 3-pass bf16 split; A [m][k] non-trans, B [k][n] trans-ldsm
static __device__ __forceinline__ void gemm128(uint32_t aH, uint32_t aL,
                                               uint32_t bH, uint32_t bL,
                                               float4 (&acc)[2][8],
                                               int wm, int wn, int lane)
{
    const int arow = 32 * wm + (lane & 7) + 8 * ((lane >> 3) & 1);
    const int acol = 8 * (lane >> 4);
    const int bkl  = lane & 15;
    const int bnl  = 64 * wn + 8 * (lane >> 4);

    #pragma unroll 1
    for (int kb = 0; kb < 8; kb++) {
        uint32_t Ah[2][4], Al[2][4];
        #pragma unroll
        for (int mi = 0; mi < 2; mi++) {
            uint32_t offA = (uint32_t)((arow + 16 * mi) * STRE + 16 * kb + acol) * 2;
            ldsm4(Ah[mi][0], Ah[mi][1], Ah[mi][2], Ah[mi][3], aH + offA);
            ldsm4(Al[mi][0], Al[mi][1], Al[mi][2], Al[mi][3], aL + offA);
        }
        #pragma unroll
        for (int j = 0; j < 4; j++) {
            uint32_t offB = (uint32_t)((16 * kb + bkl) * STRE + bnl + 16 * j) * 2;
            uint32_t bh0, bh1, bh2, bh3, bl0, bl1, bl2, bl3;
            ldsm4t(bh0, bh1, bh2, bh3, bH + offB);
            ldsm4t(bl0, bl1, bl2, bl3, bL + offB);
            #pragma unroll
            for (int mi = 0; mi < 2; mi++) {
                mma_bf16(acc[mi][2*j],   Ah[mi][0], Ah[mi][1], Ah[mi][2], Ah[mi][3], bl0, bl1);
                mma_bf16(acc[mi][2*j],   Al[mi][0], Al[mi][1], Al[mi][2], Al[mi][3], bh0, bh1);
                mma_bf16(acc[mi][2*j],   Ah[mi][0], Ah[mi][1], Ah[mi][2], Ah[mi][3], bh0, bh1);
                mma_bf16(acc[mi][2*j+1], Ah[mi][0], Ah[mi][1], Ah[mi][2], Ah[mi][3], bl2, bl3);
                mma_bf16(acc[mi][2*j+1], Al[mi][0], Al[mi][1], Al[mi][2], Al[mi][3], bh2, bh3);
                mma_bf16(acc[mi][2*j+1], Ah[mi][0], Ah[mi][1], Ah[mi][2], Ah[mi][3], bh2, bh3);
            }
        }
    }
}

__global__ void __launch_bounds__(256, 1)
gcn_kernel(const float* __restrict__ x,
           const int*   __restrict__ ei,
           const float* __restrict__ ew,
           const float* __restrict__ W1, const float* __restrict__ b1,
           const float* __restrict__ W2, const float* __restrict__ b2,
           const float* __restrict__ b7, float* __restrict__ out)
{
    extern __shared__ char smc[];
    float* sS    = (float*)(smc + OFF_S);
    float* sDinv = (float*)(smc + OFF_DINV);
    float* sBias = (float*)(smc + OFF_BIAS);

    const int g    = blockIdx.x >> 1;
    const int v    = blockIdx.x & 1;
    const int tid  = threadIdx.x;
    const int wid  = tid >> 5;
    const int lane = tid & 31;
    const int wm   = wid & 3;
    const int wn   = wid >> 2;

    const float* W   = v ? W2 : W1;
    const float* bbp = v ? b2 : b1;
    const float4 z4  = make_float4(0.f, 0.f, 0.f, 0.f);

    // init out[g] = b7[0] (mlp accumulates on top; kernel order guarantees visibility)
    if (tid == 0 && v == 0) out[g] = b7[0];

    // ---- Phase 0: zero S + pad regions only ----
    for (int i = tid; i < 3480; i += 256) ((float4*)(smc + OFF_S))[i] = z4;
    for (int i = tid; i < 116 * 6; i += 256) {           // A cols 116-127, rows 0-115
        int r = i / 6, cp = 58 + (i % 6);
        uint32_t off = (uint32_t)(r * STRE + 2 * cp) * 2;
        *(uint32_t*)(smc + OFF_AH + off) = 0u;
        *(uint32_t*)(smc + OFF_AL + off) = 0u;
    }
    for (int i = tid; i < 12 * 64; i += 256) {           // A rows 116-127
        int r = 116 + (i >> 6), cp = i & 63;
        uint32_t off = (uint32_t)(r * STRE + 2 * cp) * 2;
        *(uint32_t*)(smc + OFF_AH + off) = 0u;
        *(uint32_t*)(smc + OFF_AL + off) = 0u;
    }
    for (int i = tid; i < 13 * 64; i += 256) {           // B rows 115-127
        int r = 115 + (i >> 6), cp = i & 63;
        uint32_t off = (uint32_t)(r * STRE + 2 * cp) * 2;
        *(uint32_t*)(smc + OFF_BH + off) = 0u;
        *(uint32_t*)(smc + OFF_BL + off) = 0u;
    }
    if (tid < 128) sBias[tid] = bbp[tid];

    // ---- Phase 1: stage X -> A [m][k], W -> B [k][n]; scatter (8x batched) ----
    {
        const float* xg = x + (size_t)(g * (2 * NODES) + v * NODES) * FEAT;
        for (int i = tid; i < NODES * 58; i += 256) {
            int r = i / 58, c2 = i - r * 58;
            float f0 = xg[r * FEAT + 2 * c2];
            float f1 = (c2 < 57) ? xg[r * FEAT + 2 * c2 + 1] : 0.f;
            uint32_t hi, lo;
            split2(f0, f1, hi, lo);
            uint32_t off = (uint32_t)(r * STRE + 2 * c2) * 2;
            *(uint32_t*)(smc + OFF_AH + off) = hi;
            *(uint32_t*)(smc + OFF_AL + off) = lo;
        }
        for (int i = tid; i < (FEAT * HID) / 4; i += 256) {
            int r = i >> 5, c4 = i & 31;
            float4 w = ((const float4*)W)[i];
            uint32_t hi0, lo0, hi1, lo1;
            split2(w.x, w.y, hi0, lo0);
            split2(w.z, w.w, hi1, lo1);
            uint32_t off = (uint32_t)(r * STRE + 4 * c4) * 2;
            *(uint32_t*)(smc + OFF_BH + off)     = hi0;
            *(uint32_t*)(smc + OFF_BH + off + 4) = hi1;
            *(uint32_t*)(smc + OFF_BL + off)     = lo0;
            *(uint32_t*)(smc + OFF_BL + off + 4) = lo1;
        }
        __syncthreads();   // S zero complete before scatter
        const int ebase = g * SEG2 + v * LENN;
        const int off   = g * (2 * NODES) + v * NODES;
        const int*   eis = ei + ebase;
        const int*   eid = ei + (NB * SEG2) + ebase;
        const float* ewp = ew + ebase;
        for (int e0 = tid; e0 < 6144; e0 += 2048) {
            int   s[8]; int d[8]; float w8[8];
            #pragma unroll
            for (int j = 0; j < 8; j++) s[j]  = eis[e0 + 256 * j];
            #pragma unroll
            for (int j = 0; j < 8; j++) d[j]  = eid[e0 + 256 * j];
            #pragma unroll
            for (int j = 0; j < 8; j++) w8[j] = ewp[e0 + 256 * j];
            #pragma unroll
            for (int j = 0; j < 8; j++)
                atomicAdd(&sS[(d[j] - off) * STRS + (s[j] - off)], w8[j]);
        }
        for (int e = 6144 + tid; e < LENN; e += 256) {
            int s = eis[e] - off;
            int d = eid[e] - off;
            atomicAdd(&sS[d * STRS + s], ewp[e]);
        }
    }
    __syncthreads();

    // ---- Phase 2: dinv[r] = rsqrt(rowsum(S0)+1); rows>=116 -> 1 ----
    for (int r = wid; r < 128; r += 8) {
        float dv = 1.0f;
        if (r < NODES) {
            float s = sS[r * STRS + lane]
                    + sS[r * STRS + 32 + lane]
                    + sS[r * STRS + 64 + lane];
            if (lane < 24) s += sS[r * STRS + 96 + lane];
            #pragma unroll
            for (int o = 16; o; o >>= 1) s += __shfl_xor_sync(0xffffffffu, s, o);
            dv = rsqrtf(s + 1.0f);
        }
        if (lane == 0) sDinv[r] = dv;
    }
    __syncthreads();

    const uint32_t sb = smem_u32(smc);
    const uint32_t aH = sb + OFF_AH, aL = sb + OFF_AL;
    const uint32_t bH = sb + OFF_BH, bL = sb + OFF_BL;
    const int gr = lane >> 2;
    const int t2 = (lane & 3) * 2;

    // ---- Phase 3: GEMM1  H = X @ W ----
    float4 acc[2][8];
    #pragma unroll
    for (int mi = 0; mi < 2; mi++)
        #pragma unroll
        for (int nt = 0; nt < 8; nt++) acc[mi][nt] = z4;
    gemm128(aH, aL, bH, bL, acc, wm, wn, lane);
    __syncthreads();

    // ---- Phase 4: H' = dinv*H -> B [k=node][n=channel]; S0+I -> A ----
    #pragma unroll
    for (int mi = 0; mi < 2; mi++) {
        int r0 = 32 * wm + 16 * mi + gr;
        int r1 = r0 + 8;
        float dv0 = sDinv[r0], dv1 = sDinv[r1];
        #pragma unroll
        for (int nt = 0; nt < 8; nt++) {
            int c0 = 64 * wn + 8 * nt + t2;
            float4 a = acc[mi][nt];
            uint32_t hi, lo;
            split2(a.x * dv0, a.y * dv0, hi, lo);
            uint32_t o0 = (uint32_t)(r0 * STRE + c0) * 2;
            *(uint32_t*)(smc + OFF_BH + o0) = hi;
            *(uint32_t*)(smc + OFF_BL + o0) = lo;
            split2(a.z * dv1, a.w * dv1, hi, lo);
            uint32_t o1 = (uint32_t)(r1 * STRE + c0) * 2;
            *(uint32_t*)(smc + OFF_BH + o1) = hi;
            *(uint32_t*)(smc + OFF_BL + o1) = lo;
        }
    }
    for (int i = tid; i < 128 * 64; i += 256) {
        int r = i >> 6, c2 = i & 63;
        int c = 2 * c2;
        float f0 = 0.f, f1 = 0.f;
        if (r < NODES && c < NODES) {
            float2 s = *(float2*)(sS + r * STRS + c);
            f0 = s.x + ((r == c)     ? 1.f : 0.f);
            f1 = s.y + ((r == c + 1) ? 1.f : 0.f);
        }
        uint32_t hi, lo;
        split2(f0, f1, hi, lo);
        uint32_t off = (uint32_t)(r * STRE + c) * 2;
        *(uint32_t*)(smc + OFF_AH + off) = hi;
        *(uint32_t*)(smc + OFF_AL + off) = lo;
    }
    __syncthreads();

    // ---- Phase 5: GEMM2  out = (S0+I) @ H'; epilogue + channel-max ----
    #pragma unroll
    for (int mi = 0; mi < 2; mi++)
        #pragma unroll
        for (int nt = 0; nt < 8; nt++) acc[mi][nt] = z4;
    gemm128(aH, aL, bH, bL, acc, wm, wn, lane);

    float* sMax = sS;   // reuse: [128][2]
    #pragma unroll
    for (int mi = 0; mi < 2; mi++) {
        int r0 = 32 * wm + 16 * mi + gr;
        int r1 = r0 + 8;
        float dv0 = sDinv[r0], dv1 = sDinv[r1];
        float m0 = -3.0e38f, m1 = -3.0e38f;
        #pragma unroll
        for (int nt = 0; nt < 8; nt++) {
            int c0 = 64 * wn + 8 * nt + t2;
            float b0 = sBias[c0], b1 = sBias[c0 + 1];
            float4 a = acc[mi][nt];
            m0 = fmaxf(m0, fmaxf(fmaf(dv0, a.x, b0), fmaf(dv0, a.y, b1)));
            m1 = fmaxf(m1, fmaxf(fmaf(dv1, a.z, b0), fmaf(dv1, a.w, b1)));
        }
        m0 = fmaxf(m0, __shfl_xor_sync(0xffffffffu, m0, 1));
        m0 = fmaxf(m0, __shfl_xor_sync(0xffffffffu, m0, 2));
        m1 = fmaxf(m1, __shfl_xor_sync(0xffffffffu, m1, 1));
        m1 = fmaxf(m1, __shfl_xor_sync(0xffffffffu, m1, 2));
        if ((lane & 3) == 0) {
            sMax[2 * r0 + wn] = m0;
            sMax[2 * r1 + wn] = m1;
        }
    }
    __syncthreads();
    // write TRANSPOSED: featT[(2r+v)][g]
    for (int r = tid; r < NODES; r += 256)
        g_featT[(2 * r + v) * NB + g] = fmaxf(sMax[2 * r], sMax[2 * r + 1]);
}

// ---- MLP v2: column-partitioned. 128 CTAs x 4 cols; thread g owns graph g.
// out[g] (pre-set to b7) += sum_c relu(featT[:,g].W6[:,c] + b6[c]) * W7[c]
__global__ void __launch_bounds__(256, 1)
mlp_kernel(const float* __restrict__ W6, const float* __restrict__ b6,
           const float* __restrict__ W7, float* __restrict__ out)
{
    __shared__ float4 sW[232];     // W6[k][c0..c0+3]
    __shared__ float  sB[4], sW7[4];
    const int tid = threadIdx.x;
    const int c0  = blockIdx.x * 4;

    for (int i = tid; i < 232; i += 256)
        sW[i] = *(const float4*)(W6 + i * HC + c0);
    if (tid < 4) { sB[tid] = b6[c0 + tid]; sW7[tid] = W7[c0 + tid]; }
    __syncthreads();

    const float* fp = g_featT + tid;
    float4 acc = make_float4(0.f, 0.f, 0.f, 0.f);
    #pragma unroll 8
    for (int k = 0; k < 232; k++) {
        float  f = fp[k * NB];
        float4 w = sW[k];
        acc.x = fmaf(f, w.x, acc.x);
        acc.y = fmaf(f, w.y, acc.y);
        acc.z = fmaf(f, w.z, acc.z);
        acc.w = fmaf(f, w.w, acc.w);
    }
    float h0 = fmaxf(acc.x + sB[0], 0.f);
    float h1 = fmaxf(acc.y + sB[1], 0.f);
    float h2 = fmaxf(acc.z + sB[2], 0.f);
    float h3 = fmaxf(acc.w + sB[3], 0.f);
    float p = fmaf(h0, sW7[0], fmaf(h1, sW7[1], fmaf(h2, sW7[2], h3 * sW7[3])));
    atomicAdd(&out[tid], p);
}

extern "C" void kernel_launch(void* const* d_in, const int* in_sizes, int n_in,
                              void* d_out, int out_size)
{
    const float* x  = (const float*)d_in[0];
    const int*   ei = (const int*)  d_in[1];
    const float* ew = (const float*)d_in[2];
    // d_in[3] = batch (unused)
    const float* W1 = (const float*)d_in[4];
    const float* b1 = (const float*)d_in[5];
    const float* W2 = (const float*)d_in[6];
    const float* b2 = (const float*)d_in[7];
    const float* W6 = (const float*)d_in[8];
    const float* b6 = (const float*)d_in[9];
    const float* W7 = (const float*)d_in[10];
    const float* b7 = (const float*)d_in[11];

    cudaFuncSetAttribute(gcn_kernel, cudaFuncAttributeMaxDynamicSharedMemorySize, SMEM_BYTES);

    gcn_kernel<<<2 * NB, 256, SMEM_BYTES>>>(x, ei, ew, W1, b1, W2, b2, b7, (float*)d_out);
    mlp_kernel<<<HC / 4, 256>>>(W6, b6, W7, (float*)d_out);
}

// round 11
// speedup vs baseline: 1.3278x; 1.0608x over previous
#include <cuda_runtime.h>
#include <cuda_bf16.h>
#include <cstdint>

#define NB     256
#define NODES  116
#define FEAT   115
#define HID    128
#define LENN   6670
#define SEG2   13456
#define HC     512
#define STRS   120         // fp32 S row stride (floats)
#define STRE   136         // bf16 matrix row stride (elements)

// smem byte offsets
#define OFF_AH   0                 // A hi [128][136] bf16 (X, later S0+I)  [m][k]
#define OFF_AL   34816             // A lo
#define OFF_BH   69632             // B hi [128][136] bf16 (W, later H') — K-MAJOR [k][n]
#define OFF_BL   104448            // B lo
#define OFF_S    139264            // fp32 S 116x120 (later sMax)
#define OFF_DINV 194944            // 128 floats
#define OFF_BIAS 195456            // 128 floats
#define SMEM_BYTES 195968

__device__ float g_featT[232 * NB];   // TRANSPOSED: featT[k][g], k = 2*node + view

static __device__ __forceinline__ uint32_t smem_u32(const void* p) {
    uint32_t a;
    asm("{ .reg .u64 t; cvta.to.shared.u64 t, %1; cvt.u32.u64 %0, t; }" : "=r"(a) : "l"(p));
    return a;
}
static __device__ __forceinline__ void ldsm4(uint32_t& r0, uint32_t& r1, uint32_t& r2, uint32_t& r3,
                                             uint32_t a) {
    asm volatile("ldmatrix.sync.aligned.m8n8.x4.shared.b16 {%0,%1,%2,%3}, [%4];"
                 : "=r"(r0), "=r"(r1), "=r"(r2), "=r"(r3) : "r"(a));
}
static __device__ __forceinline__ void ldsm4t(uint32_t& r0, uint32_t& r1, uint32_t& r2, uint32_t& r3,
                                              uint32_t a) {
    asm volatile("ldmatrix.sync.aligned.m8n8.x4.trans.shared.b16 {%0,%1,%2,%3}, [%4];"
                 : "=r"(r0), "=r"(r1), "=r"(r2), "=r"(r3) : "r"(a));
}
static __device__ __forceinline__ void mma_bf16(float4& d,
                                                uint32_t a0, uint32_t a1, uint32_t a2, uint32_t a3,
                                                uint32_t b0, uint32_t b1) {
    asm volatile("mma.sync.aligned.m16n8k16.row.col.f32.bf16.bf16.f32 "
                 "{%0,%1,%2,%3},{%4,%5,%6,%7},{%8,%9},{%0,%1,%2,%3};"
                 : "+f"(d.x), "+f"(d.y), "+f"(d.z), "+f"(d.w)
                 : "r"(a0), "r"(a1), "r"(a2), "r"(a3), "r"(b0), "r"(b1));
}
// packed split: one cvt.bf16x2 for hi pair, exact hi recovery by masks, one for lo pair
static __device__ __forceinline__ void split2(float f0, float f1, uint32_t& hi, uint32_t& lo) {
    asm("cvt.rn.bf16x2.f32 %0, %1, %2;" : "=r"(hi) : "f"(f1), "f"(f0));
    float h0 = __uint_as_float(hi << 16);
    float h1 = __uint_as_float(hi & 0xFFFF0000u);
    float l0 = f0 - h0;
    float l1 = f1 - h1;
    asm("cvt.rn.bf16x2.f32 %0, %1, %2;" : "=r"(lo) : "f"(l1), "f"(l0));
}

// 128x128x128 GEMM, 3-pass bf16 split; A [m][k] non-trans, B [k][n] trans-ldsm
static __device__ __forceinline__ void gemm128(uint32_t aH, uint32_t aL,
                                               uint32_t bH, uint32_t bL,
                                               float4 (&acc)[2][8],
                                               int wm, int wn, int lane)
{
    const int arow = 32 * wm + (lane & 7) + 8 * ((lane >> 3) & 1);
    const int acol = 8 * (lane >> 4);
    const int bkl  = lane & 15;
    const int bnl  = 64 * wn + 8 * (lane >> 4);

    #pragma unroll 1
    for (int kb = 0; kb < 8; kb++) {
        uint32_t Ah[2][4], Al[2][4];
        #pragma unroll
        for (int mi = 0; mi < 2; mi++) {
            uint32_t offA = (uint32_t)((arow + 16 * mi) * STRE + 16 * kb + acol) * 2;
            ldsm4(Ah[mi][0], Ah[mi][1], Ah[mi][2], Ah[mi][3], aH + offA);
            ldsm4(Al[mi][0], Al[mi][1], Al[mi][2], Al[mi][3], aL + offA);
        }
        #pragma unroll
        for (int j = 0; j < 4; j++) {
            uint32_t offB = (uint32_t)((16 * kb + bkl) * STRE + bnl + 16 * j) * 2;
            uint32_t bh0, bh1, bh2, bh3, bl0, bl1, bl2, bl3;
            ldsm4t(bh0, bh1, bh2, bh3, bH + offB);
            ldsm4t(bl0, bl1, bl2, bl3, bL + offB);
            #pragma unroll
            for (int mi = 0; mi < 2; mi++) {
                mma_bf16(acc[mi][2*j],   Ah[mi][0], Ah[mi][1], Ah[mi][2], Ah[mi][3], bl0, bl1);
                mma_bf16(acc[mi][2*j],   Al[mi][0], Al[mi][1], Al[mi][2], Al[mi][3], bh0, bh1);
                mma_bf16(acc[mi][2*j],   Ah[mi][0], Ah[mi][1], Ah[mi][2], Ah[mi][3], bh0, bh1);
                mma_bf16(acc[mi][2*j+1], Ah[mi][0], Ah[mi][1], Ah[mi][2], Ah[mi][3], bl2, bl3);
                mma_bf16(acc[mi][2*j+1], Al[mi][0], Al[mi][1], Al[mi][2], Al[mi][3], bh2, bh3);
                mma_bf16(acc[mi][2*j+1], Ah[mi][0], Ah[mi][1], Ah[mi][2], Ah[mi][3], bh2, bh3);
            }
        }
    }
}

__global__ void __launch_bounds__(256, 1)
gcn_kernel(const float* __restrict__ x,
           const int*   __restrict__ ei,
           const float* __restrict__ ew,
           const float* __restrict__ W1, const float* __restrict__ b1,
           const float* __restrict__ W2, const float* __restrict__ b2,
           const float* __restrict__ b7, float* __restrict__ out)
{
    extern __shared__ char smc[];
    float* sS    = (float*)(smc + OFF_S);
    float* sDinv = (float*)(smc + OFF_DINV);
    float* sBias = (float*)(smc + OFF_BIAS);

    const int g    = blockIdx.x >> 1;
    const int v    = blockIdx.x & 1;
    const int tid  = threadIdx.x;
    const int wid  = tid >> 5;
    const int lane = tid & 31;
    const int wm   = wid & 3;
    const int wn   = wid >> 2;

    const float* W   = v ? W2 : W1;
    const float* bbp = v ? b2 : b1;
    const float4 z4  = make_float4(0.f, 0.f, 0.f, 0.f);

    // init out[g] = b7[0] (mlp accumulates on top)
    if (tid == 0 && v == 0) out[g] = b7[0];

    // ---- Phase 0: zero S + pad regions only ----
    for (int i = tid; i < 3480; i += 256) ((float4*)(smc + OFF_S))[i] = z4;
    for (int i = tid; i < 116 * 6; i += 256) {           // A cols 116-127, rows 0-115
        int r = i / 6, cp = 58 + (i % 6);
        uint32_t off = (uint32_t)(r * STRE + 2 * cp) * 2;
        *(uint32_t*)(smc + OFF_AH + off) = 0u;
        *(uint32_t*)(smc + OFF_AL + off) = 0u;
    }
    for (int i = tid; i < 12 * 64; i += 256) {           // A rows 116-127
        int r = 116 + (i >> 6), cp = i & 63;
        uint32_t off = (uint32_t)(r * STRE + 2 * cp) * 2;
        *(uint32_t*)(smc + OFF_AH + off) = 0u;
        *(uint32_t*)(smc + OFF_AL + off) = 0u;
    }
    for (int i = tid; i < 13 * 64; i += 256) {           // B rows 115-127
        int r = 115 + (i >> 6), cp = i & 63;
        uint32_t off = (uint32_t)(r * STRE + 2 * cp) * 2;
        *(uint32_t*)(smc + OFF_BH + off) = 0u;
        *(uint32_t*)(smc + OFF_BL + off) = 0u;
    }
    if (tid < 128) sBias[tid] = bbp[tid];

    // ---- Phase 1: stage X -> A [m][k], W -> B [k][n]; scatter (8x batched) ----
    {
        const float* xg = x + (size_t)(g * (2 * NODES) + v * NODES) * FEAT;
        for (int i = tid; i < NODES * 58; i += 256) {
            int r = i / 58, c2 = i - r * 58;
            float f0 = xg[r * FEAT + 2 * c2];
            float f1 = (c2 < 57) ? xg[r * FEAT + 2 * c2 + 1] : 0.f;
            uint32_t hi, lo;
            split2(f0, f1, hi, lo);
            uint32_t off = (uint32_t)(r * STRE + 2 * c2) * 2;
            *(uint32_t*)(smc + OFF_AH + off) = hi;
            *(uint32_t*)(smc + OFF_AL + off) = lo;
        }
        for (int i = tid; i < (FEAT * HID) / 4; i += 256) {
            int r = i >> 5, c4 = i & 31;
            float4 w = ((const float4*)W)[i];
            uint32_t hi0, lo0, hi1, lo1;
            split2(w.x, w.y, hi0, lo0);
            split2(w.z, w.w, hi1, lo1);
            uint32_t off = (uint32_t)(r * STRE + 4 * c4) * 2;
            *(uint32_t*)(smc + OFF_BH + off)     = hi0;
            *(uint32_t*)(smc + OFF_BH + off + 4) = hi1;
            *(uint32_t*)(smc + OFF_BL + off)     = lo0;
            *(uint32_t*)(smc + OFF_BL + off + 4) = lo1;
        }
        __syncthreads();   // S zero complete before scatter
        const int ebase = g * SEG2 + v * LENN;
        const int off   = g * (2 * NODES) + v * NODES;
        const int*   eis = ei + ebase;
        const int*   eid = ei + (NB * SEG2) + ebase;
        const float* ewp = ew + ebase;
        for (int e0 = tid; e0 < 6144; e0 += 2048) {
            int   s[8]; int d[8]; float w8[8];
            #pragma unroll
            for (int j = 0; j < 8; j++) s[j]  = eis[e0 + 256 * j];
            #pragma unroll
            for (int j = 0; j < 8; j++) d[j]  = eid[e0 + 256 * j];
            #pragma unroll
            for (int j = 0; j < 8; j++) w8[j] = ewp[e0 + 256 * j];
            #pragma unroll
            for (int j = 0; j < 8; j++)
                atomicAdd(&sS[(d[j] - off) * STRS + (s[j] - off)], w8[j]);
        }
        for (int e = 6144 + tid; e < LENN; e += 256) {
            int s = eis[e] - off;
            int d = eid[e] - off;
            atomicAdd(&sS[d * STRS + s], ewp[e]);
        }
    }
    __syncthreads();

    // ---- Phase 2: dinv[r] = rsqrt(rowsum(S0)+1); rows>=116 -> 1 ----
    for (int r = wid; r < 128; r += 8) {
        float dv = 1.0f;
        if (r < NODES) {
            float s = sS[r * STRS + lane]
                    + sS[r * STRS + 32 + lane]
                    + sS[r * STRS + 64 + lane];
            if (lane < 24) s += sS[r * STRS + 96 + lane];
            #pragma unroll
            for (int o = 16; o; o >>= 1) s += __shfl_xor_sync(0xffffffffu, s, o);
            dv = rsqrtf(s + 1.0f);
        }
        if (lane == 0) sDinv[r] = dv;
    }
    __syncthreads();

    const uint32_t sb = smem_u32(smc);
    const uint32_t aH = sb + OFF_AH, aL = sb + OFF_AL;
    const uint32_t bH = sb + OFF_BH, bL = sb + OFF_BL;
    const int gr = lane >> 2;
    const int t2 = (lane & 3) * 2;

    // ---- Phase 3: GEMM1  H = X @ W ----
    float4 acc[2][8];
    #pragma unroll
    for (int mi = 0; mi < 2; mi++)
        #pragma unroll
        for (int nt = 0; nt < 8; nt++) acc[mi][nt] = z4;
    gemm128(aH, aL, bH, bL, acc, wm, wn, lane);
    __syncthreads();

    // ---- Phase 4: H' = dinv*H -> B [k=node][n=channel]; S0+I -> A ----
    #pragma unroll
    for (int mi = 0; mi < 2; mi++) {
        int r0 = 32 * wm + 16 * mi + gr;
        int r1 = r0 + 8;
        float dv0 = sDinv[r0], dv1 = sDinv[r1];
        #pragma unroll
        for (int nt = 0; nt < 8; nt++) {
            int c0 = 64 * wn + 8 * nt + t2;
            float4 a = acc[mi][nt];
            uint32_t hi, lo;
            split2(a.x * dv0, a.y * dv0, hi, lo);
            uint32_t o0 = (uint32_t)(r0 * STRE + c0) * 2;
            *(uint32_t*)(smc + OFF_BH + o0) = hi;
            *(uint32_t*)(smc + OFF_BL + o0) = lo;
            split2(a.z * dv1, a.w * dv1, hi, lo);
            uint32_t o1 = (uint32_t)(r1 * STRE + c0) * 2;
            *(uint32_t*)(smc + OFF_BH + o1) = hi;
            *(uint32_t*)(smc + OFF_BL + o1) = lo;
        }
    }
    for (int i = tid; i < 128 * 64; i += 256) {
        int r = i >> 6, c2 = i & 63;
        int c = 2 * c2;
        float f0 = 0.f, f1 = 0.f;
        if (r < NODES && c < NODES) {
            float2 s = *(float2*)(sS + r * STRS + c);
            f0 = s.x + ((r == c)     ? 1.f : 0.f);
            f1 = s.y + ((r == c + 1) ? 1.f : 0.f);
        }
        uint32_t hi, lo;
        split2(f0, f1, hi, lo);
        uint32_t off = (uint32_t)(r * STRE + c) * 2;
        *(uint32_t*)(smc + OFF_AH + off) = hi;
        *(uint32_t*)(smc + OFF_AL + off) = lo;
    }
    __syncthreads();

    // ---- Phase 5: GEMM2  out = (S0+I) @ H'; epilogue + channel-max ----
    #pragma unroll
    for (int mi = 0; mi < 2; mi++)
        #pragma unroll
        for (int nt = 0; nt < 8; nt++) acc[mi][nt] = z4;
    gemm128(aH, aL, bH, bL, acc, wm, wn, lane);

    float* sMax = sS;   // reuse: [128][2]
    #pragma unroll
    for (int mi = 0; mi < 2; mi++) {
        int r0 = 32 * wm + 16 * mi + gr;
        int r1 = r0 + 8;
        float dv0 = sDinv[r0], dv1 = sDinv[r1];
        float m0 = -3.0e38f, m1 = -3.0e38f;
        #pragma unroll
        for (int nt = 0; nt < 8; nt++) {
            int c0 = 64 * wn + 8 * nt + t2;
            float b0 = sBias[c0], b1 = sBias[c0 + 1];
            float4 a = acc[mi][nt];
            m0 = fmaxf(m0, fmaxf(fmaf(dv0, a.x, b0), fmaf(dv0, a.y, b1)));
            m1 = fmaxf(m1, fmaxf(fmaf(dv1, a.z, b0), fmaf(dv1, a.w, b1)));
        }
        m0 = fmaxf(m0, __shfl_xor_sync(0xffffffffu, m0, 1));
        m0 = fmaxf(m0, __shfl_xor_sync(0xffffffffu, m0, 2));
        m1 = fmaxf(m1, __shfl_xor_sync(0xffffffffu, m1, 1));
        m1 = fmaxf(m1, __shfl_xor_sync(0xffffffffu, m1, 2));
        if ((lane & 3) == 0) {
            sMax[2 * r0 + wn] = m0;
            sMax[2 * r1 + wn] = m1;
        }
    }
    __syncthreads();
    // write TRANSPOSED: featT[(2r+v)][g]
    for (int r = tid; r < NODES; r += 256)
        g_featT[(2 * r + v) * NB + g] = fmaxf(sMax[2 * r], sMax[2 * r + 1]);
}

// ---- MLP v3: column-partitioned with float4-over-graphs + k-split ILP.
// 128 CTAs x 4 cols. 256 threads = 4 k-slices (58 k each) x 64 graph-quads.
// out[g] (pre-set to b7) += sum_c relu(featT[:,g].W6[:,c] + b6[c]) * W7[c]
__global__ void __launch_bounds__(256, 1)
mlp_kernel(const float* __restrict__ W6, const float* __restrict__ b6,
           const float* __restrict__ W7, float* __restrict__ out)
{
    __shared__ float4 sW[232];          // W6[k][c0..c0+3]
    __shared__ float4 sP[4][64][4];     // [k-slice][graph-quad][graph-in-quad] -> cols 0..3
    const int tid = threadIdx.x;
    const int c0  = blockIdx.x * 4;
    const int ks  = tid >> 6;           // k-slice 0..3
    const int gq  = tid & 63;           // graph quad: graphs 4gq..4gq+3

    for (int i = tid; i < 232; i += 256)
        sW[i] = *(const float4*)(W6 + i * HC + c0);
    __syncthreads();

    // acc[gi] = float4 over the 4 columns, for graph 4gq+gi
    float4 a0 = make_float4(0.f,0.f,0.f,0.f);
    float4 a1 = a0, a2 = a0, a3 = a0;
    const float4* fp = (const float4*)(g_featT) + gq;   // featT[k][4gq..4gq+3]
    #pragma unroll 2
    for (int kk = 0; kk < 58; kk += 2) {
        int k0 = ks * 58 + kk;
        float4 f0 = fp[k0 * 64];
        float4 f1 = fp[(k0 + 1) * 64];
        float4 w0 = sW[k0];
        float4 w1 = sW[k0 + 1];
        a0.x = fmaf(f0.x, w0.x, a0.x); a0.y = fmaf(f0.x, w0.y, a0.y);
        a0.z = fmaf(f0.x, w0.z, a0.z); a0.w = fmaf(f0.x, w0.w, a0.w);
        a1.x = fmaf(f0.y, w0.x, a1.x); a1.y = fmaf(f0.y, w0.y, a1.y);
        a1.z = fmaf(f0.y, w0.z, a1.z); a1.w = fmaf(f0.y, w0.w, a1.w);
        a2.x = fmaf(f0.z, w0.x, a2.x); a2.y = fmaf(f0.z, w0.y, a2.y);
        a2.z = fmaf(f0.z, w0.z, a2.z); a2.w = fmaf(f0.z, w0.w, a2.w);
        a3.x = fmaf(f0.w, w0.x, a3.x); a3.y = fmaf(f0.w, w0.y, a3.y);
        a3.z = fmaf(f0.w, w0.z, a3.z); a3.w = fmaf(f0.w, w0.w, a3.w);
        a0.x = fmaf(f1.x, w1.x, a0.x); a0.y = fmaf(f1.x, w1.y, a0.y);
        a0.z = fmaf(f1.x, w1.z, a0.z); a0.w = fmaf(f1.x, w1.w, a0.w);
        a1.x = fmaf(f1.y, w1.x, a1.x); a1.y = fmaf(f1.y, w1.y, a1.y);
        a1.z = fmaf(f1.y, w1.z, a1.z); a1.w = fmaf(f1.y, w1.w, a1.w);
        a2.x = fmaf(f1.z, w1.x, a2.x); a2.y = fmaf(f1.z, w1.y, a2.y);
        a2.z = fmaf(f1.z, w1.z, a2.z); a2.w = fmaf(f1.z, w1.w, a2.w);
        a3.x = fmaf(f1.w, w1.x, a3.x); a3.y = fmaf(f1.w, w1.y, a3.y);
        a3.z = fmaf(f1.w, w1.z, a3.z); a3.w = fmaf(f1.w, w1.w, a3.w);
    }
    sP[ks][gq][0] = a0;
    sP[ks][gq][1] = a1;
    sP[ks][gq][2] = a2;
    sP[ks][gq][3] = a3;
    __syncthreads();

    // combine k-slices: thread owns (gq2 = tid>>2, gi = tid&3) -> graph 4*gq2+gi
    {
        const int gq2 = tid >> 2;
        const int gi  = tid & 3;
        float4 s0 = sP[0][gq2][gi];
        float4 s1 = sP[1][gq2][gi];
        float4 s2 = sP[2][gq2][gi];
        float4 s3 = sP[3][gq2][gi];
        float4 bv = *(const float4*)(b6 + c0);
        float4 wv = *(const float4*)(W7 + c0);
        float h0 = fmaxf(s0.x + s1.x + s2.x + s3.x + bv.x, 0.f);
        float h1 = fmaxf(s0.y + s1.y + s2.y + s3.y + bv.y, 0.f);
        float h2 = fmaxf(s0.z + s1.z + s2.z + s3.z + bv.z, 0.f);
        float h3 = fmaxf(s0.w + s1.w + s2.w + s3.w + bv.w, 0.f);
        float p = fmaf(h0, wv.x, fmaf(h1, wv.y, fmaf(h2, wv.z, h3 * wv.w)));
        atomicAdd(&out[4 * gq2 + gi], p);
    }
}

extern "C" void kernel_launch(void* const* d_in, const int* in_sizes, int n_in,
                              void* d_out, int out_size)
{
    const float* x  = (const float*)d_in[0];
    const int*   ei = (const int*)  d_in[1];
    const float* ew = (const float*)d_in[2];
    // d_in[3] = batch (unused)
    const float* W1 = (const float*)d_in[4];
    const float* b1 = (const float*)d_in[5];
    const float* W2 = (const float*)d_in[6];
    const float* b2 = (const float*)d_in[7];
    const float* W6 = (const float*)d_in[8];
    const float* b6 = (const float*)d_in[9];
    const float* W7 = (const float*)d_in[10];
    const float* b7 = (const float*)d_in[11];

    cudaFuncSetAttribute(gcn_kernel, cudaFuncAttributeMaxDynamicSharedMemorySize, SMEM_BYTES);

    gcn_kernel<<<2 * NB, 256, SMEM_BYTES>>>(x, ei, ew, W1, b1, W2, b2, b7, (float*)d_out);
    mlp_kernel<<<HC / 4, 256>>>(W6, b6, W7, (float*)d_out);
}

// round 12
// speedup vs baseline: 1.4595x; 1.0992x over previous
#include <cuda_runtime.h>
#include <cuda_fp16.h>
#include <cstdint>

#define NB     256
#define NODES  116
#define FEAT   115
#define HID    128
#define LENN   6670
#define SEG2   13456
#define HC     512
#define STRS   120         // fp32 S row stride (floats)
#define STRE   136         // fp16 matrix row stride (elements)

// smem byte offsets
#define OFF_AH   0                 // A fp16 (hi only) [128][136] (X, later S0+I)  [m][k]
#define OFF_BH   34816             // B hi [128][136] (W, later H') — K-MAJOR [k][n]
#define OFF_BL   69632             // B lo
#define OFF_S    104448            // fp32 S 116x120 (later sMax)
#define OFF_DINV 160128            // 128 floats
#define OFF_BIAS 160640            // 128 floats
#define SMEM_BYTES 161152

__device__ float g_featT[232 * NB];   // TRANSPOSED: featT[k][g], k = 2*node + view

static __device__ __forceinline__ uint32_t smem_u32(const void* p) {
    uint32_t a;
    asm("{ .reg .u64 t; cvta.to.shared.u64 t, %1; cvt.u32.u64 %0, t; }" : "=r"(a) : "l"(p));
    return a;
}
static __device__ __forceinline__ void ldsm4(uint32_t& r0, uint32_t& r1, uint32_t& r2, uint32_t& r3,
                                             uint32_t a) {
    asm volatile("ldmatrix.sync.aligned.m8n8.x4.shared.b16 {%0,%1,%2,%3}, [%4];"
                 : "=r"(r0), "=r"(r1), "=r"(r2), "=r"(r3) : "r"(a));
}
static __device__ __forceinline__ void ldsm4t(uint32_t& r0, uint32_t& r1, uint32_t& r2, uint32_t& r3,
                                              uint32_t a) {
    asm volatile("ldmatrix.sync.aligned.m8n8.x4.trans.shared.b16 {%0,%1,%2,%3}, [%4];"
                 : "=r"(r0), "=r"(r1), "=r"(r2), "=r"(r3) : "r"(a));
}
static __device__ __forceinline__ void mma_f16(float4& d,
                                               uint32_t a0, uint32_t a1, uint32_t a2, uint32_t a3,
                                               uint32_t b0, uint32_t b1) {
    asm volatile("mma.sync.aligned.m16n8k16.row.col.f32.f16.f16.f32 "
                 "{%0,%1,%2,%3},{%4,%5,%6,%7},{%8,%9},{%0,%1,%2,%3};"
                 : "+f"(d.x), "+f"(d.y), "+f"(d.z), "+f"(d.w)
                 : "r"(a0), "r"(a1), "r"(a2), "r"(a3), "r"(b0), "r"(b1));
}
// fp16 pack of a float pair (memory order: f0 = low half)
static __device__ __forceinline__ uint32_t pack2h(float f0, float f1) {
    __half2 h = __floats2half2_rn(f0, f1);
    return *(uint32_t*)&h;
}
// fp16 hi/lo split of a float pair
static __device__ __forceinline__ void split2(float f0, float f1, uint32_t& hi, uint32_t& lo) {
    __half2 h = __floats2half2_rn(f0, f1);
    float2 hf = __half22float2(h);
    __half2 l = __floats2half2_rn(f0 - hf.x, f1 - hf.y);
    hi = *(uint32_t*)&h;
    lo = *(uint32_t*)&l;
}

// 128x128x128 GEMM: A fp16 (hi only), B fp16 hi+lo; acc += Ah*(Bl+Bh)
static __device__ __forceinline__ void gemm128(uint32_t aH, uint32_t bH, uint32_t bL,
                                               float4 (&acc)[2][8],
                                               int wm, int wn, int lane)
{
    const int arow = 32 * wm + (lane & 7) + 8 * ((lane >> 3) & 1);
    const int acol = 8 * (lane >> 4);
    const int bkl  = lane & 15;
    const int bnl  = 64 * wn + 8 * (lane >> 4);

    #pragma unroll 1
    for (int kb = 0; kb < 8; kb++) {
        uint32_t Ah[2][4];
        #pragma unroll
        for (int mi = 0; mi < 2; mi++) {
            uint32_t offA = (uint32_t)((arow + 16 * mi) * STRE + 16 * kb + acol) * 2;
            ldsm4(Ah[mi][0], Ah[mi][1], Ah[mi][2], Ah[mi][3], aH + offA);
        }
        #pragma unroll
        for (int j = 0; j < 4; j++) {
            uint32_t offB = (uint32_t)((16 * kb + bkl) * STRE + bnl + 16 * j) * 2;
            uint32_t bh0, bh1, bh2, bh3, bl0, bl1, bl2, bl3;
            ldsm4t(bh0, bh1, bh2, bh3, bH + offB);
            ldsm4t(bl0, bl1, bl2, bl3, bL + offB);
            #pragma unroll
            for (int mi = 0; mi < 2; mi++) {
                mma_f16(acc[mi][2*j],   Ah[mi][0], Ah[mi][1], Ah[mi][2], Ah[mi][3], bl0, bl1);
                mma_f16(acc[mi][2*j],   Ah[mi][0], Ah[mi][1], Ah[mi][2], Ah[mi][3], bh0, bh1);
                mma_f16(acc[mi][2*j+1], Ah[mi][0], Ah[mi][1], Ah[mi][2], Ah[mi][3], bl2, bl3);
                mma_f16(acc[mi][2*j+1], Ah[mi][0], Ah[mi][1], Ah[mi][2], Ah[mi][3], bh2, bh3);
            }
        }
    }
}

__global__ void __launch_bounds__(256, 1)
gcn_kernel(const float* __restrict__ x,
           const int*   __restrict__ ei,
           const float* __restrict__ ew,
           const float* __restrict__ W1, const float* __restrict__ b1,
           const float* __restrict__ W2, const float* __restrict__ b2,
           const float* __restrict__ b7, float* __restrict__ out)
{
    extern __shared__ char smc[];
    float* sS    = (float*)(smc + OFF_S);
    float* sDinv = (float*)(smc + OFF_DINV);
    float* sBias = (float*)(smc + OFF_BIAS);

    const int g    = blockIdx.x >> 1;
    const int v    = blockIdx.x & 1;
    const int tid  = threadIdx.x;
    const int wid  = tid >> 5;
    const int lane = tid & 31;
    const int wm   = wid & 3;
    const int wn   = wid >> 2;

    const float* W   = v ? W2 : W1;
    const float* bbp = v ? b2 : b1;
    const float4 z4  = make_float4(0.f, 0.f, 0.f, 0.f);

    // init out[g] = b7[0] (mlp accumulates on top)
    if (tid == 0 && v == 0) out[g] = b7[0];

    // ---- Phase 0: zero S + pad regions only ----
    for (int i = tid; i < 3480; i += 256) ((float4*)(smc + OFF_S))[i] = z4;
    for (int i = tid; i < 116 * 6; i += 256) {           // A cols 116-127, rows 0-115
        int r = i / 6, cp = 58 + (i % 6);
        *(uint32_t*)(smc + OFF_AH + (uint32_t)(r * STRE + 2 * cp) * 2) = 0u;
    }
    for (int i = tid; i < 12 * 64; i += 256) {           // A rows 116-127
        int r = 116 + (i >> 6), cp = i & 63;
        *(uint32_t*)(smc + OFF_AH + (uint32_t)(r * STRE + 2 * cp) * 2) = 0u;
    }
    for (int i = tid; i < 13 * 64; i += 256) {           // B rows 115-127
        int r = 115 + (i >> 6), cp = i & 63;
        uint32_t off = (uint32_t)(r * STRE + 2 * cp) * 2;
        *(uint32_t*)(smc + OFF_BH + off) = 0u;
        *(uint32_t*)(smc + OFF_BL + off) = 0u;
    }
    if (tid < 128) sBias[tid] = bbp[tid];

    // ---- Phase 1: stage X -> A fp16 [m][k], W -> B hi/lo [k][n]; scatter ----
    {
        const float* xg = x + (size_t)(g * (2 * NODES) + v * NODES) * FEAT;
        for (int i = tid; i < NODES * 58; i += 256) {
            int r = i / 58, c2 = i - r * 58;
            float f0 = xg[r * FEAT + 2 * c2];
            float f1 = (c2 < 57) ? xg[r * FEAT + 2 * c2 + 1] : 0.f;
            *(uint32_t*)(smc + OFF_AH + (uint32_t)(r * STRE + 2 * c2) * 2) = pack2h(f0, f1);
        }
        for (int i = tid; i < (FEAT * HID) / 4; i += 256) {
            int r = i >> 5, c4 = i & 31;
            float4 w = ((const float4*)W)[i];
            uint32_t hi0, lo0, hi1, lo1;
            split2(w.x, w.y, hi0, lo0);
            split2(w.z, w.w, hi1, lo1);
            uint32_t off = (uint32_t)(r * STRE + 4 * c4) * 2;
            *(uint32_t*)(smc + OFF_BH + off)     = hi0;
            *(uint32_t*)(smc + OFF_BH + off + 4) = hi1;
            *(uint32_t*)(smc + OFF_BL + off)     = lo0;
            *(uint32_t*)(smc + OFF_BL + off + 4) = lo1;
        }
        __syncthreads();   // S zero complete before scatter
        const int ebase = g * SEG2 + v * LENN;
        const int off   = g * (2 * NODES) + v * NODES;
        const int*   eis = ei + ebase;
        const int*   eid = ei + (NB * SEG2) + ebase;
        const float* ewp = ew + ebase;
        for (int e0 = tid; e0 < 6144; e0 += 2048) {
            int   s[8]; int d[8]; float w8[8];
            #pragma unroll
            for (int j = 0; j < 8; j++) s[j]  = eis[e0 + 256 * j];
            #pragma unroll
            for (int j = 0; j < 8; j++) d[j]  = eid[e0 + 256 * j];
            #pragma unroll
            for (int j = 0; j < 8; j++) w8[j] = ewp[e0 + 256 * j];
            #pragma unroll
            for (int j = 0; j < 8; j++)
                atomicAdd(&sS[(d[j] - off) * STRS + (s[j] - off)], w8[j]);
        }
        for (int e = 6144 + tid; e < LENN; e += 256) {
            int s = eis[e] - off;
            int d = eid[e] - off;
            atomicAdd(&sS[d * STRS + s], ewp[e]);
        }
    }
    __syncthreads();

    // ---- Phase 2: dinv[r] = rsqrt(rowsum(S0)+1); rows>=116 -> 1 ----
    for (int r = wid; r < 128; r += 8) {
        float dv = 1.0f;
        if (r < NODES) {
            float s = sS[r * STRS + lane]
                    + sS[r * STRS + 32 + lane]
                    + sS[r * STRS + 64 + lane];
            if (lane < 24) s += sS[r * STRS + 96 + lane];
            #pragma unroll
            for (int o = 16; o; o >>= 1) s += __shfl_xor_sync(0xffffffffu, s, o);
            dv = rsqrtf(s + 1.0f);
        }
        if (lane == 0) sDinv[r] = dv;
    }
    __syncthreads();

    const uint32_t sb = smem_u32(smc);
    const uint32_t aH = sb + OFF_AH;
    const uint32_t bH = sb + OFF_BH, bL = sb + OFF_BL;
    const int gr = lane >> 2;
    const int t2 = (lane & 3) * 2;

    // ---- Phase 3: GEMM1  H = X @ W ----
    float4 acc[2][8];
    #pragma unroll
    for (int mi = 0; mi < 2; mi++)
        #pragma unroll
        for (int nt = 0; nt < 8; nt++) acc[mi][nt] = z4;
    gemm128(aH, bH, bL, acc, wm, wn, lane);
    __syncthreads();

    // ---- Phase 4: H' = dinv*H -> B hi/lo [k=node][n=channel]; S0+I -> A fp16 ----
    #pragma unroll
    for (int mi = 0; mi < 2; mi++) {
        int r0 = 32 * wm + 16 * mi + gr;
        int r1 = r0 + 8;
        float dv0 = sDinv[r0], dv1 = sDinv[r1];
        #pragma unroll
        for (int nt = 0; nt < 8; nt++) {
            int c0 = 64 * wn + 8 * nt + t2;
            float4 a = acc[mi][nt];
            uint32_t hi, lo;
            split2(a.x * dv0, a.y * dv0, hi, lo);
            uint32_t o0 = (uint32_t)(r0 * STRE + c0) * 2;
            *(uint32_t*)(smc + OFF_BH + o0) = hi;
            *(uint32_t*)(smc + OFF_BL + o0) = lo;
            split2(a.z * dv1, a.w * dv1, hi, lo);
            uint32_t o1 = (uint32_t)(r1 * STRE + c0) * 2;
            *(uint32_t*)(smc + OFF_BH + o1) = hi;
            *(uint32_t*)(smc + OFF_BL + o1) = lo;
        }
    }
    for (int i = tid; i < 128 * 64; i += 256) {
        int r = i >> 6, c2 = i & 63;
        int c = 2 * c2;
        float f0 = 0.f, f1 = 0.f;
        if (r < NODES && c < NODES) {
            float2 s = *(float2*)(sS + r * STRS + c);
            f0 = s.x + ((r == c)     ? 1.f : 0.f);
            f1 = s.y + ((r == c + 1) ? 1.f : 0.f);
        }
        *(uint32_t*)(smc + OFF_AH + (uint32_t)(r * STRE + c) * 2) = pack2h(f0, f1);
    }
    __syncthreads();

    // ---- Phase 5: GEMM2  out = (S0+I) @ H'; epilogue + channel-max ----
    #pragma unroll
    for (int mi = 0; mi < 2; mi++)
        #pragma unroll
        for (int nt = 0; nt < 8; nt++) acc[mi][nt] = z4;
    gemm128(aH, bH, bL, acc, wm, wn, lane);

    float* sMax = sS;   // reuse: [128][2]
    #pragma unroll
    for (int mi = 0; mi < 2; mi++) {
        int r0 = 32 * wm + 16 * mi + gr;
        int r1 = r0 + 8;
        float dv0 = sDinv[r0], dv1 = sDinv[r1];
        float m0 = -3.0e38f, m1 = -3.0e38f;
        #pragma unroll
        for (int nt = 0; nt < 8; nt++) {
            int c0 = 64 * wn + 8 * nt + t2;
            float b0 = sBias[c0], b1 = sBias[c0 + 1];
            float4 a = acc[mi][nt];
            m0 = fmaxf(m0, fmaxf(fmaf(dv0, a.x, b0), fmaf(dv0, a.y, b1)));
            m1 = fmaxf(m1, fmaxf(fmaf(dv1, a.z, b0), fmaf(dv1, a.w, b1)));
        }
        m0 = fmaxf(m0, __shfl_xor_sync(0xffffffffu, m0, 1));
        m0 = fmaxf(m0, __shfl_xor_sync(0xffffffffu, m0, 2));
        m1 = fmaxf(m1, __shfl_xor_sync(0xffffffffu, m1, 1));
        m1 = fmaxf(m1, __shfl_xor_sync(0xffffffffu, m1, 2));
        if ((lane & 3) == 0) {
            sMax[2 * r0 + wn] = m0;
            sMax[2 * r1 + wn] = m1;
        }
    }
    __syncthreads();
    // write TRANSPOSED: featT[(2r+v)][g]
    for (int r = tid; r < NODES; r += 256)
        g_featT[(2 * r + v) * NB + g] = fmaxf(sMax[2 * r], sMax[2 * r + 1]);
}

// ---- MLP v4: column-partitioned, 512 threads = 8 k-slices x 64 graph-quads.
// 128 CTAs x 4 cols; out[g] (pre-set to b7) += relu(featT.W6+b6).W7 partial
__global__ void __launch_bounds__(512, 1)
mlp_kernel(const float* __restrict__ W6, const float* __restrict__ b6,
           const float* __restrict__ W7, float* __restrict__ out)
{
    __shared__ float4 sW[232];          // W6[k][c0..c0+3]
    __shared__ float4 sP[8][64][4];     // [k-slice][graph-quad][graph-in-quad]
    const int tid = threadIdx.x;
    const int c0  = blockIdx.x * 4;
    const int ks  = tid >> 6;           // k-slice 0..7 (29 k each)
    const int gq  = tid & 63;           // graph quad

    for (int i = tid; i < 232; i += 512)
        sW[i] = *(const float4*)(W6 + i * HC + c0);
    __syncthreads();

    float4 a0 = make_float4(0.f,0.f,0.f,0.f);
    float4 a1 = a0, a2 = a0, a3 = a0;
    const float4* fp = (const float4*)(g_featT) + gq;
    const int kbase = ks * 29;
    #pragma unroll 1
    for (int kk = 0; kk < 28; kk += 2) {
        int k0 = kbase + kk;
        float4 f0 = fp[k0 * 64];
        float4 f1 = fp[(k0 + 1) * 64];
        float4 w0 = sW[k0];
        float4 w1 = sW[k0 + 1];
        a0.x = fmaf(f0.x, w0.x, a0.x); a0.y = fmaf(f0.x, w0.y, a0.y);
        a0.z = fmaf(f0.x, w0.z, a0.z); a0.w = fmaf(f0.x, w0.w, a0.w);
        a1.x = fmaf(f0.y, w0.x, a1.x); a1.y = fmaf(f0.y, w0.y, a1.y);
        a1.z = fmaf(f0.y, w0.z, a1.z); a1.w = fmaf(f0.y, w0.w, a1.w);
        a2.x = fmaf(f0.z, w0.x, a2.x); a2.y = fmaf(f0.z, w0.y, a2.y);
        a2.z = fmaf(f0.z, w0.z, a2.z); a2.w = fmaf(f0.z, w0.w, a2.w);
        a3.x = fmaf(f0.w, w0.x, a3.x); a3.y = fmaf(f0.w, w0.y, a3.y);
        a3.z = fmaf(f0.w, w0.z, a3.z); a3.w = fmaf(f0.w, w0.w, a3.w);
        a0.x = fmaf(f1.x, w1.x, a0.x); a0.y = fmaf(f1.x, w1.y, a0.y);
        a0.z = fmaf(f1.x, w1.z, a0.z); a0.w = fmaf(f1.x, w1.w, a0.w);
        a1.x = fmaf(f1.y, w1.x, a1.x); a1.y = fmaf(f1.y, w1.y, a1.y);
        a1.z = fmaf(f1.y, w1.z, a1.z); a1.w = fmaf(f1.y, w1.w, a1.w);
        a2.x = fmaf(f1.z, w1.x, a2.x); a2.y = fmaf(f1.z, w1.y, a2.y);
        a2.z = fmaf(f1.z, w1.z, a2.z); a2.w = fmaf(f1.z, w1.w, a2.w);
        a3.x = fmaf(f1.w, w1.x, a3.x); a3.y = fmaf(f1.w, w1.y, a3.y);
        a3.z = fmaf(f1.w, w1.z, a3.z); a3.w = fmaf(f1.w, w1.w, a3.w);
    }
    {   // k tail (29th element of the slice)
        int k0 = kbase + 28;
        float4 f0 = fp[k0 * 64];
        float4 w0 = sW[k0];
        a0.x = fmaf(f0.x, w0.x, a0.x); a0.y = fmaf(f0.x, w0.y, a0.y);
        a0.z = fmaf(f0.x, w0.z, a0.z); a0.w = fmaf(f0.x, w0.w, a0.w);
        a1.x = fmaf(f0.y, w0.x, a1.x); a1.y = fmaf(f0.y, w0.y, a1.y);
        a1.z = fmaf(f0.y, w0.z, a1.z); a1.w = fmaf(f0.y, w0.w, a1.w);
        a2.x = fmaf(f0.z, w0.x, a2.x); a2.y = fmaf(f0.z, w0.y, a2.y);
        a2.z = fmaf(f0.z, w0.z, a2.z); a2.w = fmaf(f0.z, w0.w, a2.w);
        a3.x = fmaf(f0.w, w0.x, a3.x); a3.y = fmaf(f0.w, w0.y, a3.y);
        a3.z = fmaf(f0.w, w0.z, a3.z); a3.w = fmaf(f0.w, w0.w, a3.w);
    }
    sP[ks][gq][0] = a0;
    sP[ks][gq][1] = a1;
    sP[ks][gq][2] = a2;
    sP[ks][gq][3] = a3;
    __syncthreads();

    // combine 8 k-slices: thread tid<256 owns graph tid
    if (tid < 256) {
        const int gq2 = tid >> 2;
        const int gi  = tid & 3;
        float4 s = sP[0][gq2][gi];
        #pragma unroll
        for (int k = 1; k < 8; k++) {
            float4 t = sP[k][gq2][gi];
            s.x += t.x; s.y += t.y; s.z += t.z; s.w += t.w;
        }
        float4 bv = *(const float4*)(b6 + c0);
        float4 wv = *(const float4*)(W7 + c0);
        float h0 = fmaxf(s.x + bv.x, 0.f);
        float h1 = fmaxf(s.y + bv.y, 0.f);
        float h2 = fmaxf(s.z + bv.z, 0.f);
        float h3 = fmaxf(s.w + bv.w, 0.f);
        float p = fmaf(h0, wv.x, fmaf(h1, wv.y, fmaf(h2, wv.z, h3 * wv.w)));
        atomicAdd(&out[tid], p);
    }
}

extern "C" void kernel_launch(void* const* d_in, const int* in_sizes, int n_in,
                              void* d_out, int out_size)
{
    const float* x  = (const float*)d_in[0];
    const int*   ei = (const int*)  d_in[1];
    const float* ew = (const float*)d_in[2];
    // d_in[3] = batch (unused)
    const float* W1 = (const float*)d_in[4];
    const float* b1 = (const float*)d_in[5];
    const float* W2 = (const float*)d_in[6];
    const float* b2 = (const float*)d_in[7];
    const float* W6 = (const float*)d_in[8];
    const float* b6 = (const float*)d_in[9];
    const float* W7 = (const float*)d_in[10];
    const float* b7 = (const float*)d_in[11];

    cudaFuncSetAttribute(gcn_kernel, cudaFuncAttributeMaxDynamicSharedMemorySize, SMEM_BYTES);

    gcn_kernel<<<2 * NB, 256, SMEM_BYTES>>>(x, ei, ew, W1, b1, W2, b2, b7, (float*)d_out);
    mlp_kernel<<<HC / 4, 512>>>(W6, b6, W7, (float*)d_out);
}

// round 13
// speedup vs baseline: 1.5258x; 1.0454x over previous
#include <cuda_runtime.h>
#include <cuda_fp16.h>
#include <cstdint>

#define NB     256
#define NODES  116
#define FEAT   115
#define HID    128
#define LENN   6670
#define SEG2   13456
#define HC     512
#define STRS   120         // fp32 S row stride (floats)
#define STRE   136         // fp16 matrix row stride (elements)

// smem byte offsets
#define OFF_AH   0                 // A fp16 [128][136] (X, later S0+I)  [m][k]
#define OFF_BH   34816             // B hi [128][136] (W, later H') — K-MAJOR [k][n]
#define OFF_BL   69632             // B lo
#define OFF_S    104448            // fp32 S 116x120 (later sMax)
#define OFF_DINV 160128            // 128 floats
#define OFF_BIAS 160640            // 128 floats
#define SMEM_BYTES 161152

__device__ float g_featT[232 * NB];   // TRANSPOSED: featT[k][g]

static __device__ __forceinline__ uint32_t smem_u32(const void* p) {
    uint32_t a;
    asm("{ .reg .u64 t; cvta.to.shared.u64 t, %1; cvt.u32.u64 %0, t; }" : "=r"(a) : "l"(p));
    return a;
}
static __device__ __forceinline__ void ldsm4(uint32_t& r0, uint32_t& r1, uint32_t& r2, uint32_t& r3,
                                             uint32_t a) {
    asm volatile("ldmatrix.sync.aligned.m8n8.x4.shared.b16 {%0,%1,%2,%3}, [%4];"
                 : "=r"(r0), "=r"(r1), "=r"(r2), "=r"(r3) : "r"(a));
}
static __device__ __forceinline__ void ldsm4t(uint32_t& r0, uint32_t& r1, uint32_t& r2, uint32_t& r3,
                                              uint32_t a) {
    asm volatile("ldmatrix.sync.aligned.m8n8.x4.trans.shared.b16 {%0,%1,%2,%3}, [%4];"
                 : "=r"(r0), "=r"(r1), "=r"(r2), "=r"(r3) : "r"(a));
}
static __device__ __forceinline__ void mma_f16(float4& d,
                                               uint32_t a0, uint32_t a1, uint32_t a2, uint32_t a3,
                                               uint32_t b0, uint32_t b1) {
    asm volatile("mma.sync.aligned.m16n8k16.row.col.f32.f16.f16.f32 "
                 "{%0,%1,%2,%3},{%4,%5,%6,%7},{%8,%9},{%0,%1,%2,%3};"
                 : "+f"(d.x), "+f"(d.y), "+f"(d.z), "+f"(d.w)
                 : "r"(a0), "r"(a1), "r"(a2), "r"(a3), "r"(b0), "r"(b1));
}
static __device__ __forceinline__ uint32_t pack2h(float f0, float f1) {
    __half2 h = __floats2half2_rn(f0, f1);
    return *(uint32_t*)&h;
}
static __device__ __forceinline__ void split2(float f0, float f1, uint32_t& hi, uint32_t& lo) {
    __half2 h = __floats2half2_rn(f0, f1);
    float2 hf = __half22float2(h);
    __half2 l = __floats2half2_rn(f0 - hf.x, f1 - hf.y);
    hi = *(uint32_t*)&h;
    lo = *(uint32_t*)&l;
}

// 128x128x128 GEMM: A fp16 (hi only), B fp16 hi+lo; acc += Ah*(Bl+Bh)
static __device__ __forceinline__ void gemm128(uint32_t aH, uint32_t bH, uint32_t bL,
                                               float4 (&acc)[2][8],
                                               int wm, int wn, int lane)
{
    const int arow = 32 * wm + (lane & 7) + 8 * ((lane >> 3) & 1);
    const int acol = 8 * (lane >> 4);
    const int bkl  = lane & 15;
    const int bnl  = 64 * wn + 8 * (lane >> 4);

    #pragma unroll 1
    for (int kb = 0; kb < 8; kb++) {
        uint32_t Ah[2][4];
        #pragma unroll
        for (int mi = 0; mi < 2; mi++) {
            uint32_t offA = (uint32_t)((arow + 16 * mi) * STRE + 16 * kb + acol) * 2;
            ldsm4(Ah[mi][0], Ah[mi][1], Ah[mi][2], Ah[mi][3], aH + offA);
        }
        #pragma unroll
        for (int j = 0; j < 4; j++) {
            uint32_t offB = (uint32_t)((16 * kb + bkl) * STRE + bnl + 16 * j) * 2;
            uint32_t bh0, bh1, bh2, bh3, bl0, bl1, bl2, bl3;
            ldsm4t(bh0, bh1, bh2, bh3, bH + offB);
            ldsm4t(bl0, bl1, bl2, bl3, bL + offB);
            #pragma unroll
            for (int mi = 0; mi < 2; mi++) {
                mma_f16(acc[mi][2*j],   Ah[mi][0], Ah[mi][1], Ah[mi][2], Ah[mi][3], bl0, bl1);
                mma_f16(acc[mi][2*j],   Ah[mi][0], Ah[mi][1], Ah[mi][2], Ah[mi][3], bh0, bh1);
                mma_f16(acc[mi][2*j+1], Ah[mi][0], Ah[mi][1], Ah[mi][2], Ah[mi][3], bl2, bl3);
                mma_f16(acc[mi][2*j+1], Ah[mi][0], Ah[mi][1], Ah[mi][2], Ah[mi][3], bh2, bh3);
            }
        }
    }
}

__global__ void __launch_bounds__(256, 1)
gcn_kernel(const float* __restrict__ x,
           const int*   __restrict__ ei,
           const float* __restrict__ ew,
           const float* __restrict__ W1, const float* __restrict__ b1,
           const float* __restrict__ W2, const float* __restrict__ b2,
           const float* __restrict__ b7, float* __restrict__ out)
{
    extern __shared__ char smc[];
    float* sS    = (float*)(smc + OFF_S);
    float* sDinv = (float*)(smc + OFF_DINV);
    float* sBias = (float*)(smc + OFF_BIAS);

    const int g    = blockIdx.x >> 1;
    const int v    = blockIdx.x & 1;
    const int tid  = threadIdx.x;
    const int wid  = tid >> 5;
    const int lane = tid & 31;
    const int wm   = wid & 3;
    const int wn   = wid >> 2;

    const float* W   = v ? W2 : W1;
    const float* bbp = v ? b2 : b1;
    const float4 z4  = make_float4(0.f, 0.f, 0.f, 0.f);

    if (tid == 0 && v == 0) out[g] = b7[0];

    // edge pointers (used by the pipelined scatter)
    const int ebase = g * SEG2 + v * LENN;
    const int eoff  = g * (2 * NODES) + v * NODES;
    const int*   eis = ei + ebase;
    const int*   eid = ei + (NB * SEG2) + ebase;
    const float* ewp = ew + ebase;

    // ---- prefetch scatter super-batch A (edges tid + 256j, j<8) ----
    int sA[8], dA[8]; float wA[8];
    #pragma unroll
    for (int j = 0; j < 8; j++) sA[j] = eis[tid + 256 * j];
    #pragma unroll
    for (int j = 0; j < 8; j++) dA[j] = eid[tid + 256 * j];
    #pragma unroll
    for (int j = 0; j < 8; j++) wA[j] = ewp[tid + 256 * j];

    // ---- Phase 0: zero S + pad regions ----
    for (int i = tid; i < 3480; i += 256) ((float4*)(smc + OFF_S))[i] = z4;
    for (int i = tid; i < 116 * 6; i += 256) {
        int r = i / 6, cp = 58 + (i % 6);
        *(uint32_t*)(smc + OFF_AH + (uint32_t)(r * STRE + 2 * cp) * 2) = 0u;
    }
    for (int i = tid; i < 12 * 64; i += 256) {
        int r = 116 + (i >> 6), cp = i & 63;
        *(uint32_t*)(smc + OFF_AH + (uint32_t)(r * STRE + 2 * cp) * 2) = 0u;
    }
    for (int i = tid; i < 13 * 64; i += 256) {
        int r = 115 + (i >> 6), cp = i & 63;
        uint32_t off = (uint32_t)(r * STRE + 2 * cp) * 2;
        *(uint32_t*)(smc + OFF_BH + off) = 0u;
        *(uint32_t*)(smc + OFF_BL + off) = 0u;
    }
    if (tid < 128) sBias[tid] = bbp[tid];

    // ---- Phase 1: stage X -> A fp16, W -> B hi/lo; pipelined scatter ----
    {
        const float* xg = x + (size_t)(g * (2 * NODES) + v * NODES) * FEAT;
        for (int i = tid; i < NODES * 58; i += 256) {
            int r = i / 58, c2 = i - r * 58;
            float f0 = xg[r * FEAT + 2 * c2];
            float f1 = (c2 < 57) ? xg[r * FEAT + 2 * c2 + 1] : 0.f;
            *(uint32_t*)(smc + OFF_AH + (uint32_t)(r * STRE + 2 * c2) * 2) = pack2h(f0, f1);
        }
        for (int i = tid; i < (FEAT * HID) / 4; i += 256) {
            int r = i >> 5, c4 = i & 31;
            float4 w = ((const float4*)W)[i];
            uint32_t hi0, lo0, hi1, lo1;
            split2(w.x, w.y, hi0, lo0);
            split2(w.z, w.w, hi1, lo1);
            uint32_t off = (uint32_t)(r * STRE + 4 * c4) * 2;
            *(uint32_t*)(smc + OFF_BH + off)     = hi0;
            *(uint32_t*)(smc + OFF_BH + off + 4) = hi1;
            *(uint32_t*)(smc + OFF_BL + off)     = lo0;
            *(uint32_t*)(smc + OFF_BL + off + 4) = lo1;
        }
        __syncthreads();   // S zero complete before atomics

        // batch B prefetch, then atomics A
        int sB[8], dB[8]; float wB[8];
        #pragma unroll
        for (int j = 0; j < 8; j++) sB[j] = eis[tid + 2048 + 256 * j];
        #pragma unroll
        for (int j = 0; j < 8; j++) dB[j] = eid[tid + 2048 + 256 * j];
        #pragma unroll
        for (int j = 0; j < 8; j++) wB[j] = ewp[tid + 2048 + 256 * j];
        #pragma unroll
        for (int j = 0; j < 8; j++)
            atomicAdd(&sS[(dA[j] - eoff) * STRS + (sA[j] - eoff)], wA[j]);

        // batch C prefetch, then atomics B, then atomics C
        int sC[8], dC[8]; float wC[8];
        #pragma unroll
        for (int j = 0; j < 8; j++) sC[j] = eis[tid + 4096 + 256 * j];
        #pragma unroll
        for (int j = 0; j < 8; j++) dC[j] = eid[tid + 4096 + 256 * j];
        #pragma unroll
        for (int j = 0; j < 8; j++) wC[j] = ewp[tid + 4096 + 256 * j];
        #pragma unroll
        for (int j = 0; j < 8; j++)
            atomicAdd(&sS[(dB[j] - eoff) * STRS + (sB[j] - eoff)], wB[j]);
        #pragma unroll
        for (int j = 0; j < 8; j++)
            atomicAdd(&sS[(dC[j] - eoff) * STRS + (sC[j] - eoff)], wC[j]);

        for (int e = 6144 + tid; e < LENN; e += 256) {
            int s = eis[e] - eoff;
            int d = eid[e] - eoff;
            atomicAdd(&sS[d * STRS + s], ewp[e]);
        }
    }
    __syncthreads();

    // ---- Phase 2: dinv[r] = rsqrt(rowsum(S0)+1); rows>=116 -> 1 ----
    for (int r = wid; r < 128; r += 8) {
        float dv = 1.0f;
        if (r < NODES) {
            float s = sS[r * STRS + lane]
                    + sS[r * STRS + 32 + lane]
                    + sS[r * STRS + 64 + lane];
            if (lane < 24) s += sS[r * STRS + 96 + lane];
            #pragma unroll
            for (int o = 16; o; o >>= 1) s += __shfl_xor_sync(0xffffffffu, s, o);
            dv = rsqrtf(s + 1.0f);
        }
        if (lane == 0) sDinv[r] = dv;
    }
    __syncthreads();

    const uint32_t sb = smem_u32(smc);
    const uint32_t aH = sb + OFF_AH;
    const uint32_t bH = sb + OFF_BH, bL = sb + OFF_BL;
    const int gr = lane >> 2;
    const int t2 = (lane & 3) * 2;

    // ---- Phase 3: GEMM1  H = X @ W ----
    float4 acc[2][8];
    #pragma unroll
    for (int mi = 0; mi < 2; mi++)
        #pragma unroll
        for (int nt = 0; nt < 8; nt++) acc[mi][nt] = z4;
    gemm128(aH, bH, bL, acc, wm, wn, lane);
    __syncthreads();

    // ---- Phase 4: H' = dinv*H -> B hi/lo [k=node][n=channel]; S0+I -> A fp16 ----
    #pragma unroll
    for (int mi = 0; mi < 2; mi++) {
        int r0 = 32 * wm + 16 * mi + gr;
        int r1 = r0 + 8;
        float dv0 = sDinv[r0], dv1 = sDinv[r1];
        #pragma unroll
        for (int nt = 0; nt < 8; nt++) {
            int c0 = 64 * wn + 8 * nt + t2;
            float4 a = acc[mi][nt];
            uint32_t hi, lo;
            split2(a.x * dv0, a.y * dv0, hi, lo);
            uint32_t o0 = (uint32_t)(r0 * STRE + c0) * 2;
            *(uint32_t*)(smc + OFF_BH + o0) = hi;
            *(uint32_t*)(smc + OFF_BL + o0) = lo;
            split2(a.z * dv1, a.w * dv1, hi, lo);
            uint32_t o1 = (uint32_t)(r1 * STRE + c0) * 2;
            *(uint32_t*)(smc + OFF_BH + o1) = hi;
            *(uint32_t*)(smc + OFF_BL + o1) = lo;
        }
    }
    for (int i = tid; i < 128 * 64; i += 256) {
        int r = i >> 6, c2 = i & 63;
        int c = 2 * c2;
        float f0 = 0.f, f1 = 0.f;
        if (r < NODES && c < NODES) {
            float2 s = *(float2*)(sS + r * STRS + c);
            f0 = s.x + ((r == c)     ? 1.f : 0.f);
            f1 = s.y + ((r == c + 1) ? 1.f : 0.f);
        }
        *(uint32_t*)(smc + OFF_AH + (uint32_t)(r * STRE + c) * 2) = pack2h(f0, f1);
    }
    __syncthreads();

    // ---- Phase 5: GEMM2  out = (S0+I) @ H'; epilogue + channel-max ----
    #pragma unroll
    for (int mi = 0; mi < 2; mi++)
        #pragma unroll
        for (int nt = 0; nt < 8; nt++) acc[mi][nt] = z4;
    gemm128(aH, bH, bL, acc, wm, wn, lane);

    float* sMax = sS;
    #pragma unroll
    for (int mi = 0; mi < 2; mi++) {
        int r0 = 32 * wm + 16 * mi + gr;
        int r1 = r0 + 8;
        float dv0 = sDinv[r0], dv1 = sDinv[r1];
        float m0 = -3.0e38f, m1 = -3.0e38f;
        #pragma unroll
        for (int nt = 0; nt < 8; nt++) {
            int c0 = 64 * wn + 8 * nt + t2;
            float b0 = sBias[c0], b1 = sBias[c0 + 1];
            float4 a = acc[mi][nt];
            m0 = fmaxf(m0, fmaxf(fmaf(dv0, a.x, b0), fmaf(dv0, a.y, b1)));
            m1 = fmaxf(m1, fmaxf(fmaf(dv1, a.z, b0), fmaf(dv1, a.w, b1)));
        }
        m0 = fmaxf(m0, __shfl_xor_sync(0xffffffffu, m0, 1));
        m0 = fmaxf(m0, __shfl_xor_sync(0xffffffffu, m0, 2));
        m1 = fmaxf(m1, __shfl_xor_sync(0xffffffffu, m1, 1));
        m1 = fmaxf(m1, __shfl_xor_sync(0xffffffffu, m1, 2));
        if ((lane & 3) == 0) {
            sMax[2 * r0 + wn] = m0;
            sMax[2 * r1 + wn] = m1;
        }
    }
    __syncthreads();
    for (int r = tid; r < NODES; r += 256)
        g_featT[(2 * r + v) * NB + g] = fmaxf(sMax[2 * r], sMax[2 * r + 1]);
}

// ---- MLP v5: column-partitioned, 512 threads = 8 k-slices x 64 graph-quads.
// 4-way load batching in the k loop (MLP>=4).
#define FMA16(F, Wv)                                                 \
    a0.x = fmaf(F.x, Wv.x, a0.x); a0.y = fmaf(F.x, Wv.y, a0.y);      \
    a0.z = fmaf(F.x, Wv.z, a0.z); a0.w = fmaf(F.x, Wv.w, a0.w);      \
    a1.x = fmaf(F.y, Wv.x, a1.x); a1.y = fmaf(F.y, Wv.y, a1.y);      \
    a1.z = fmaf(F.y, Wv.z, a1.z); a1.w = fmaf(F.y, Wv.w, a1.w);      \
    a2.x = fmaf(F.z, Wv.x, a2.x); a2.y = fmaf(F.z, Wv.y, a2.y);      \
    a2.z = fmaf(F.z, Wv.z, a2.z); a2.w = fmaf(F.z, Wv.w, a2.w);      \
    a3.x = fmaf(F.w, Wv.x, a3.x); a3.y = fmaf(F.w, Wv.y, a3.y);      \
    a3.z = fmaf(F.w, Wv.z, a3.z); a3.w = fmaf(F.w, Wv.w, a3.w);

__global__ void __launch_bounds__(512, 1)
mlp_kernel(const float* __restrict__ W6, const float* __restrict__ b6,
           const float* __restrict__ W7, float* __restrict__ out)
{
    __shared__ float4 sW[232];
    __shared__ float4 sP[8][64][4];
    const int tid = threadIdx.x;
    const int c0  = blockIdx.x * 4;
    const int ks  = tid >> 6;
    const int gq  = tid & 63;

    for (int i = tid; i < 232; i += 512)
        sW[i] = *(const float4*)(W6 + i * HC + c0);
    __syncthreads();

    float4 a0 = make_float4(0.f,0.f,0.f,0.f);
    float4 a1 = a0, a2 = a0, a3 = a0;
    const float4* fp = (const float4*)(g_featT) + gq;
    const int kbase = ks * 29;
    #pragma unroll 1
    for (int kk = 0; kk < 28; kk += 4) {
        int k0 = kbase + kk;
        float4 f0 = fp[(k0 + 0) * 64];
        float4 f1 = fp[(k0 + 1) * 64];
        float4 f2 = fp[(k0 + 2) * 64];
        float4 f3 = fp[(k0 + 3) * 64];
        float4 w0 = sW[k0 + 0];
        float4 w1 = sW[k0 + 1];
        float4 w2 = sW[k0 + 2];
        float4 w3 = sW[k0 + 3];
        FMA16(f0, w0)
        FMA16(f1, w1)
        FMA16(f2, w2)
        FMA16(f3, w3)
    }
    {   // 29th element
        int k0 = kbase + 28;
        float4 f0 = fp[k0 * 64];
        float4 w0 = sW[k0];
        FMA16(f0, w0)
    }
    sP[ks][gq][0] = a0;
    sP[ks][gq][1] = a1;
    sP[ks][gq][2] = a2;
    sP[ks][gq][3] = a3;
    __syncthreads();

    if (tid < 256) {
        const int gq2 = tid >> 2;
        const int gi  = tid & 3;
        float4 s = sP[0][gq2][gi];
        #pragma unroll
        for (int k = 1; k < 8; k++) {
            float4 t = sP[k][gq2][gi];
            s.x += t.x; s.y += t.y; s.z += t.z; s.w += t.w;
        }
        float4 bv = *(const float4*)(b6 + c0);
        float4 wv = *(const float4*)(W7 + c0);
        float h0 = fmaxf(s.x + bv.x, 0.f);
        float h1 = fmaxf(s.y + bv.y, 0.f);
        float h2 = fmaxf(s.z + bv.z, 0.f);
        float h3 = fmaxf(s.w + bv.w, 0.f);
        float p = fmaf(h0, wv.x, fmaf(h1, wv.y, fmaf(h2, wv.z, h3 * wv.w)));
        atomicAdd(&out[tid], p);
    }
}

extern "C" void kernel_launch(void* const* d_in, const int* in_sizes, int n_in,
                              void* d_out, int out_size)
{
    const float* x  = (const float*)d_in[0];
    const int*   ei = (const int*)  d_in[1];
    const float* ew = (const float*)d_in[2];
    // d_in[3] = batch (unused)
    const float* W1 = (const float*)d_in[4];
    const float* b1 = (const float*)d_in[5];
    const float* W2 = (const float*)d_in[6];
    const float* b2 = (const float*)d_in[7];
    const float* W6 = (const float*)d_in[8];
    const float* b6 = (const float*)d_in[9];
    const float* W7 = (const float*)d_in[10];
    const float* b7 = (const float*)d_in[11];

    cudaFuncSetAttribute(gcn_kernel, cudaFuncAttributeMaxDynamicSharedMemorySize, SMEM_BYTES);

    gcn_kernel<<<2 * NB, 256, SMEM_BYTES>>>(x, ei, ew, W1, b1, W2, b2, b7, (float*)d_out);
    mlp_kernel<<<HC / 4, 512>>>(W6, b6, W7, (float*)d_out);
}

// round 14
// speedup vs baseline: 2.2542x; 1.4773x over previous
#include <cuda_runtime.h>
#include <cuda_fp16.h>
#include <cstdint>

#define NB     256
#define NODES  116
#define FEAT   115
#define HID    128
#define LENN   6670
#define SEG2   13456
#define HC     512
#define STRE   136         // fp16 matrix row stride (elements)

// smem byte offsets (occ-2 layout: NO fp32 S buffer)
#define OFF_AH   0                 // A fp16 [128][136] (X, then scatter target S0+I)
#define OFF_BH   34816             // B hi [128][136] (W, later H') — K-MAJOR [k][n]
#define OFF_BL   69632             // B lo
#define OFF_MAX  104448            // float [128][2]
#define OFF_DINV 105472            // 128 floats
#define OFF_BIAS 105984            // 128 floats
#define SMEM_BYTES 106496          // x2 CTAs = 212992 < 227KB

__device__ float g_featT[232 * NB];   // TRANSPOSED: featT[k][g]

static __device__ __forceinline__ uint32_t smem_u32(const void* p) {
    uint32_t a;
    asm("{ .reg .u64 t; cvta.to.shared.u64 t, %1; cvt.u32.u64 %0, t; }" : "=r"(a) : "l"(p));
    return a;
}
static __device__ __forceinline__ void ldsm4(uint32_t& r0, uint32_t& r1, uint32_t& r2, uint32_t& r3,
                                             uint32_t a) {
    asm volatile("ldmatrix.sync.aligned.m8n8.x4.shared.b16 {%0,%1,%2,%3}, [%4];"
                 : "=r"(r0), "=r"(r1), "=r"(r2), "=r"(r3) : "r"(a));
}
static __device__ __forceinline__ void ldsm4t(uint32_t& r0, uint32_t& r1, uint32_t& r2, uint32_t& r3,
                                              uint32_t a) {
    asm volatile("ldmatrix.sync.aligned.m8n8.x4.trans.shared.b16 {%0,%1,%2,%3}, [%4];"
                 : "=r"(r0), "=r"(r1), "=r"(r2), "=r"(r3) : "r"(a));
}
static __device__ __forceinline__ void mma_f16(float4& d,
                                               uint32_t a0, uint32_t a1, uint32_t a2, uint32_t a3,
                                               uint32_t b0, uint32_t b1) {
    asm volatile("mma.sync.aligned.m16n8k16.row.col.f32.f16.f16.f32 "
                 "{%0,%1,%2,%3},{%4,%5,%6,%7},{%8,%9},{%0,%1,%2,%3};"
                 : "+f"(d.x), "+f"(d.y), "+f"(d.z), "+f"(d.w)
                 : "r"(a0), "r"(a1), "r"(a2), "r"(a3), "r"(b0), "r"(b1));
}
static __device__ __forceinline__ uint32_t pack2h(float f0, float f1) {
    __half2 h = __floats2half2_rn(f0, f1);
    return *(uint32_t*)&h;
}
static __device__ __forceinline__ void split2(float f0, float f1, uint32_t& hi, uint32_t& lo) {
    __half2 h = __floats2half2_rn(f0, f1);
    float2 hf = __half22float2(h);
    __half2 l = __floats2half2_rn(f0 - hf.x, f1 - hf.y);
    hi = *(uint32_t*)&h;
    lo = *(uint32_t*)&l;
}
static __device__ __forceinline__ float ldh(const char* smc, int idx) {
    return __half2float(*(const __half*)(smc + OFF_AH + idx * 2));
}

// 128x128x128 GEMM: A fp16 (hi only), B fp16 hi+lo; acc += Ah*(Bl+Bh)
static __device__ __forceinline__ void gemm128(uint32_t aH, uint32_t bH, uint32_t bL,
                                               float4 (&acc)[2][8],
                                               int wm, int wn, int lane)
{
    const int arow = 32 * wm + (lane & 7) + 8 * ((lane >> 3) & 1);
    const int acol = 8 * (lane >> 4);
    const int bkl  = lane & 15;
    const int bnl  = 64 * wn + 8 * (lane >> 4);

    #pragma unroll 1
    for (int kb = 0; kb < 8; kb++) {
        uint32_t Ah[2][4];
        #pragma unroll
        for (int mi = 0; mi < 2; mi++) {
            uint32_t offA = (uint32_t)((arow + 16 * mi) * STRE + 16 * kb + acol) * 2;
            ldsm4(Ah[mi][0], Ah[mi][1], Ah[mi][2], Ah[mi][3], aH + offA);
        }
        #pragma unroll
        for (int j = 0; j < 4; j++) {
            uint32_t offB = (uint32_t)((16 * kb + bkl) * STRE + bnl + 16 * j) * 2;
            uint32_t bh0, bh1, bh2, bh3, bl0, bl1, bl2, bl3;
            ldsm4t(bh0, bh1, bh2, bh3, bH + offB);
            ldsm4t(bl0, bl1, bl2, bl3, bL + offB);
            #pragma unroll
            for (int mi = 0; mi < 2; mi++) {
                mma_f16(acc[mi][2*j],   Ah[mi][0], Ah[mi][1], Ah[mi][2], Ah[mi][3], bl0, bl1);
                mma_f16(acc[mi][2*j],   Ah[mi][0], Ah[mi][1], Ah[mi][2], Ah[mi][3], bh0, bh1);
                mma_f16(acc[mi][2*j+1], Ah[mi][0], Ah[mi][1], Ah[mi][2], Ah[mi][3], bl2, bl3);
                mma_f16(acc[mi][2*j+1], Ah[mi][0], Ah[mi][1], Ah[mi][2], Ah[mi][3], bh2, bh3);
            }
        }
    }
}

__global__ void __launch_bounds__(256, 2)
gcn_kernel(const float* __restrict__ x,
           const int*   __restrict__ ei,
           const float* __restrict__ ew,
           const float* __restrict__ W1, const float* __restrict__ b1,
           const float* __restrict__ W2, const float* __restrict__ b2,
           const float* __restrict__ b7, float* __restrict__ out)
{
    extern __shared__ char smc[];
    float* sMax  = (float*)(smc + OFF_MAX);
    float* sDinv = (float*)(smc + OFF_DINV);
    float* sBias = (float*)(smc + OFF_BIAS);

    const int g    = blockIdx.x >> 1;
    const int v    = blockIdx.x & 1;
    const int tid  = threadIdx.x;
    const int wid  = tid >> 5;
    const int lane = tid & 31;
    const int wm   = wid & 3;
    const int wn   = wid >> 2;

    const float* W   = v ? W2 : W1;
    const float* bbp = v ? b2 : b1;
    const float4 z4  = make_float4(0.f, 0.f, 0.f, 0.f);

    if (tid == 0 && v == 0) out[g] = b7[0];

    // ---- Phase 0: zero A pads + B pads; bias ----
    for (int i = tid; i < 116 * 6; i += 256) {           // A cols 116-127, rows 0-115
        int r = i / 6, cp = 58 + (i % 6);
        *(uint32_t*)(smc + OFF_AH + (uint32_t)(r * STRE + 2 * cp) * 2) = 0u;
    }
    for (int i = tid; i < 12 * 64; i += 256) {           // A rows 116-127
        int r = 116 + (i >> 6), cp = i & 63;
        *(uint32_t*)(smc + OFF_AH + (uint32_t)(r * STRE + 2 * cp) * 2) = 0u;
    }
    for (int i = tid; i < 13 * 64; i += 256) {           // B rows 115-127
        int r = 115 + (i >> 6), cp = i & 63;
        uint32_t off = (uint32_t)(r * STRE + 2 * cp) * 2;
        *(uint32_t*)(smc + OFF_BH + off) = 0u;
        *(uint32_t*)(smc + OFF_BL + off) = 0u;
    }
    if (tid < 128) sBias[tid] = bbp[tid];

    // ---- Phase 1: stage X -> A fp16, W -> B hi/lo ----
    {
        const float* xg = x + (size_t)(g * (2 * NODES) + v * NODES) * FEAT;
        for (int i = tid; i < NODES * 58; i += 256) {
            int r = i / 58, c2 = i - r * 58;
            float f0 = xg[r * FEAT + 2 * c2];
            float f1 = (c2 < 57) ? xg[r * FEAT + 2 * c2 + 1] : 0.f;
            *(uint32_t*)(smc + OFF_AH + (uint32_t)(r * STRE + 2 * c2) * 2) = pack2h(f0, f1);
        }
        for (int i = tid; i < (FEAT * HID) / 4; i += 256) {
            int r = i >> 5, c4 = i & 31;
            float4 w = ((const float4*)W)[i];
            uint32_t hi0, lo0, hi1, lo1;
            split2(w.x, w.y, hi0, lo0);
            split2(w.z, w.w, hi1, lo1);
            uint32_t off = (uint32_t)(r * STRE + 4 * c4) * 2;
            *(uint32_t*)(smc + OFF_BH + off)     = hi0;
            *(uint32_t*)(smc + OFF_BH + off + 4) = hi1;
            *(uint32_t*)(smc + OFF_BL + off)     = lo0;
            *(uint32_t*)(smc + OFF_BL + off + 4) = lo1;
        }
    }
    __syncthreads();

    const uint32_t sb = smem_u32(smc);
    const uint32_t aH = sb + OFF_AH;
    const uint32_t bH = sb + OFF_BH, bL = sb + OFF_BL;
    const int gr = lane >> 2;
    const int t2 = (lane & 3) * 2;

    // ---- Phase 2: GEMM1  H = X @ W (acc stays in registers) ----
    float4 acc[2][8];
    #pragma unroll
    for (int mi = 0; mi < 2; mi++)
        #pragma unroll
        for (int nt = 0; nt < 8; nt++) acc[mi][nt] = z4;
    gemm128(aH, bH, bL, acc, wm, wn, lane);
    __syncthreads();   // all reads of A done

    // ---- Phase 3: zero full A ----
    for (int i = tid; i < 34816 / 16; i += 256) ((float4*)(smc + OFF_AH))[i] = z4;
    __syncthreads();

    // ---- Phase 4: scatter edges into A as fp16 half2 atomics ----
    {
        const int ebase = g * SEG2 + v * LENN;
        const int eoff  = g * (2 * NODES) + v * NODES;
        const int*   eis = ei + ebase;
        const int*   eid = ei + (NB * SEG2) + ebase;
        const float* ewp = ew + ebase;
        for (int e0 = tid; e0 < 6144; e0 += 2048) {
            int sE[8], dE[8]; float wE[8];
            #pragma unroll
            for (int j = 0; j < 8; j++) sE[j] = eis[e0 + 256 * j];
            #pragma unroll
            for (int j = 0; j < 8; j++) dE[j] = eid[e0 + 256 * j];
            #pragma unroll
            for (int j = 0; j < 8; j++) wE[j] = ewp[e0 + 256 * j];
            #pragma unroll
            for (int j = 0; j < 8; j++) {
                int off = (dE[j] - eoff) * STRE + (sE[j] - eoff);
                __half wh = __float2half(wE[j]);
                __half2 val = (off & 1) ? __halves2half2(__float2half(0.f), wh)
                                        : __halves2half2(wh, __float2half(0.f));
                atomicAdd((__half2*)(smc + OFF_AH + (uint32_t)(off & ~1) * 2), val);
            }
        }
        for (int e = 6144 + tid; e < LENN; e += 256) {
            int off = (eid[e] - eoff) * STRE + (eis[e] - eoff);
            __half wh = __float2half(ewp[e]);
            __half2 val = (off & 1) ? __halves2half2(__float2half(0.f), wh)
                                    : __halves2half2(wh, __float2half(0.f));
            atomicAdd((__half2*)(smc + OFF_AH + (uint32_t)(off & ~1) * 2), val);
        }
    }
    __syncthreads();

    // ---- Phase 5: dinv[r] = rsqrt(rowsum(A[r]) + 1); add self-loop diag ----
    for (int r = wid; r < 128; r += 8) {
        float dv = 1.0f;
        if (r < NODES) {
            float s = ldh(smc, r * STRE + lane)
                    + ldh(smc, r * STRE + 32 + lane)
                    + ldh(smc, r * STRE + 64 + lane)
                    + ldh(smc, r * STRE + 96 + lane);   // pads are zero
            #pragma unroll
            for (int o = 16; o; o >>= 1) s += __shfl_xor_sync(0xffffffffu, s, o);
            dv = rsqrtf(s + 1.0f);
            if (lane == 0) {
                __half* dp = (__half*)(smc + OFF_AH + (uint32_t)(r * STRE + r) * 2);
                *dp = __float2half(__half2float(*dp) + 1.0f);
            }
        }
        if (lane == 0) sDinv[r] = dv;
    }
    __syncthreads();

    // ---- Phase 6: H' = dinv*H -> B hi/lo [k=node][n=channel] ----
    #pragma unroll
    for (int mi = 0; mi < 2; mi++) {
        int r0 = 32 * wm + 16 * mi + gr;
        int r1 = r0 + 8;
        float dv0 = sDinv[r0], dv1 = sDinv[r1];
        #pragma unroll
        for (int nt = 0; nt < 8; nt++) {
            int c0 = 64 * wn + 8 * nt + t2;
            float4 a = acc[mi][nt];
            uint32_t hi, lo;
            split2(a.x * dv0, a.y * dv0, hi, lo);
            uint32_t o0 = (uint32_t)(r0 * STRE + c0) * 2;
            *(uint32_t*)(smc + OFF_BH + o0) = hi;
            *(uint32_t*)(smc + OFF_BL + o0) = lo;
            split2(a.z * dv1, a.w * dv1, hi, lo);
            uint32_t o1 = (uint32_t)(r1 * STRE + c0) * 2;
            *(uint32_t*)(smc + OFF_BH + o1) = hi;
            *(uint32_t*)(smc + OFF_BL + o1) = lo;
        }
    }
    __syncthreads();

    // ---- Phase 7: GEMM2  out = (S0+I) @ H'; epilogue + channel-max ----
    #pragma unroll
    for (int mi = 0; mi < 2; mi++)
        #pragma unroll
        for (int nt = 0; nt < 8; nt++) acc[mi][nt] = z4;
    gemm128(aH, bH, bL, acc, wm, wn, lane);

    #pragma unroll
    for (int mi = 0; mi < 2; mi++) {
        int r0 = 32 * wm + 16 * mi + gr;
        int r1 = r0 + 8;
        float dv0 = sDinv[r0], dv1 = sDinv[r1];
        float m0 = -3.0e38f, m1 = -3.0e38f;
        #pragma unroll
        for (int nt = 0; nt < 8; nt++) {
            int c0 = 64 * wn + 8 * nt + t2;
            float b0 = sBias[c0], b1 = sBias[c0 + 1];
            float4 a = acc[mi][nt];
            m0 = fmaxf(m0, fmaxf(fmaf(dv0, a.x, b0), fmaf(dv0, a.y, b1)));
            m1 = fmaxf(m1, fmaxf(fmaf(dv1, a.z, b0), fmaf(dv1, a.w, b1)));
        }
        m0 = fmaxf(m0, __shfl_xor_sync(0xffffffffu, m0, 1));
        m0 = fmaxf(m0, __shfl_xor_sync(0xffffffffu, m0, 2));
        m1 = fmaxf(m1, __shfl_xor_sync(0xffffffffu, m1, 1));
        m1 = fmaxf(m1, __shfl_xor_sync(0xffffffffu, m1, 2));
        if ((lane & 3) == 0) {
            sMax[2 * r0 + wn] = m0;
            sMax[2 * r1 + wn] = m1;
        }
    }
    __syncthreads();
    for (int r = tid; r < NODES; r += 256)
        g_featT[(2 * r + v) * NB + g] = fmaxf(sMax[2 * r], sMax[2 * r + 1]);
}

// ---- MLP v6: 128 CTAs x 4 cols; 1024 threads = 16 k-slices x 64 graph-quads ----
#define FMA16(F, Wv)                                                 \
    a0.x = fmaf(F.x, Wv.x, a0.x); a0.y = fmaf(F.x, Wv.y, a0.y);      \
    a0.z = fmaf(F.x, Wv.z, a0.z); a0.w = fmaf(F.x, Wv.w, a0.w);      \
    a1.x = fmaf(F.y, Wv.x, a1.x); a1.y = fmaf(F.y, Wv.y, a1.y);      \
    a1.z = fmaf(F.y, Wv.z, a1.z); a1.w = fmaf(F.y, Wv.w, a1.w);      \
    a2.x = fmaf(F.z, Wv.x, a2.x); a2.y = fmaf(F.z, Wv.y, a2.y);      \
    a2.z = fmaf(F.z, Wv.z, a2.z); a2.w = fmaf(F.z, Wv.w, a2.w);      \
    a3.x = fmaf(F.w, Wv.x, a3.x); a3.y = fmaf(F.w, Wv.y, a3.y);      \
    a3.z = fmaf(F.w, Wv.z, a3.z); a3.w = fmaf(F.w, Wv.w, a3.w);

#define MLP_SMEM ((232 + 16 * 64 * 4) * 16)

__global__ void __launch_bounds__(1024, 1)
mlp_kernel(const float* __restrict__ W6, const float* __restrict__ b6,
           const float* __restrict__ W7, float* __restrict__ out)
{
    extern __shared__ float4 dyn[];
    float4* sW = dyn;            // [232]
    float4* sP = dyn + 232;      // [16][64][4]
    const int tid = threadIdx.x;
    const int c0  = blockIdx.x * 4;
    const int ks  = tid >> 6;           // 0..15
    const int gq  = tid & 63;

    if (tid < 232) sW[tid] = *(const float4*)(W6 + tid * HC + c0);
    __syncthreads();

    float4 a0 = make_float4(0.f,0.f,0.f,0.f);
    float4 a1 = a0, a2 = a0, a3 = a0;
    const float4* fp = (const float4*)(g_featT) + gq;
    const int len   = (ks < 8) ? 15 : 14;
    const int kbase = (ks < 8) ? 15 * ks : 120 + 14 * (ks - 8);
    int kk = 0;
    #pragma unroll 1
    for (; kk + 4 <= len; kk += 4) {
        int k0 = kbase + kk;
        float4 f0 = fp[(k0 + 0) * 64];
        float4 f1 = fp[(k0 + 1) * 64];
        float4 f2 = fp[(k0 + 2) * 64];
        float4 f3 = fp[(k0 + 3) * 64];
        float4 w0 = sW[k0 + 0];
        float4 w1 = sW[k0 + 1];
        float4 w2 = sW[k0 + 2];
        float4 w3 = sW[k0 + 3];
        FMA16(f0, w0)
        FMA16(f1, w1)
        FMA16(f2, w2)
        FMA16(f3, w3)
    }
    {   // tail (2 or 3)
        int k0 = kbase + kk;
        float4 f0 = fp[(k0 + 0) * 64];
        float4 f1 = fp[(k0 + 1) * 64];
        float4 w0 = sW[k0 + 0];
        float4 w1 = sW[k0 + 1];
        FMA16(f0, w0)
        FMA16(f1, w1)
        if (kk + 3 <= len) {
            float4 f2 = fp[(k0 + 2) * 64];
            float4 w2 = sW[k0 + 2];
            FMA16(f2, w2)
        }
    }
    float4* pp = sP + (ks * 64 + gq) * 4;
    pp[0] = a0; pp[1] = a1; pp[2] = a2; pp[3] = a3;
    __syncthreads();

    if (tid < 256) {
        const int gq2 = tid >> 2;
        const int gi  = tid & 3;
        float4 s = sP[(0 * 64 + gq2) * 4 + gi];
        #pragma unroll
        for (int k = 1; k < 16; k++) {
            float4 t = sP[(k * 64 + gq2) * 4 + gi];
            s.x += t.x; s.y += t.y; s.z += t.z; s.w += t.w;
        }
        float4 bv = *(const float4*)(b6 + c0);
        float4 wv = *(const float4*)(W7 + c0);
        float h0 = fmaxf(s.x + bv.x, 0.f);
        float h1 = fmaxf(s.y + bv.y, 0.f);
        float h2 = fmaxf(s.z + bv.z, 0.f);
        float h3 = fmaxf(s.w + bv.w, 0.f);
        float p = fmaf(h0, wv.x, fmaf(h1, wv.y, fmaf(h2, wv.z, h3 * wv.w)));
        atomicAdd(&out[tid], p);
    }
}

extern "C" void kernel_launch(void* const* d_in, const int* in_sizes, int n_in,
                              void* d_out, int out_size)
{
    const float* x  = (const float*)d_in[0];
    const int*   ei = (const int*)  d_in[1];
    const float* ew = (const float*)d_in[2];
    // d_in[3] = batch (unused)
    const float* W1 = (const float*)d_in[4];
    const float* b1 = (const float*)d_in[5];
    const float* W2 = (const float*)d_in[6];
    const float* b2 = (const float*)d_in[7];
    const float* W6 = (const float*)d_in[8];
    const float* b6 = (const float*)d_in[9];
    const float* W7 = (const float*)d_in[10];
    const float* b7 = (const float*)d_in[11];

    cudaFuncSetAttribute(gcn_kernel, cudaFuncAttributeMaxDynamicSharedMemorySize, SMEM_BYTES);
    cudaFuncSetAttribute(mlp_kernel, cudaFuncAttributeMaxDynamicSharedMemorySize, MLP_SMEM);

    gcn_kernel<<<2 * NB, 256, SMEM_BYTES>>>(x, ei, ew, W1, b1, W2, b2, b7, (float*)d_out);
    mlp_kernel<<<HC / 4, 1024, MLP_SMEM>>>(W6, b6, W7, (float*)d_out);
}

// round 15
// speedup vs baseline: 2.3387x; 1.0375x over previous
#include <cuda_runtime.h>
#include <cuda_fp16.h>
#include <cstdint>

#define NB     256
#define NODES  116
#define FEAT   115
#define HID    128
#define LENN   6670
#define SEG2   13456
#define HC     512
#define STRE   136         // fp16 matrix row stride (elements)

// smem byte offsets (occ-2 layout)
#define OFF_AH   0                 // A fp16 [128][136] (X, then scatter target S0+I)
#define OFF_BH   34816             // B hi [128][136] (W, later H') — K-MAJOR [k][n]
#define OFF_BL   69632             // B lo (W only; GEMM2 is hi-only)
#define OFF_MAX  104448            // float [128][2]
#define OFF_DINV 105472            // 128 floats
#define OFF_BIAS 105984            // 128 floats
#define SMEM_BYTES 106496          // x2 CTAs = 212992 < 227KB

__device__ float g_featT[232 * NB];   // TRANSPOSED: featT[k][g]

static __device__ __forceinline__ uint32_t smem_u32(const void* p) {
    uint32_t a;
    asm("{ .reg .u64 t; cvta.to.shared.u64 t, %1; cvt.u32.u64 %0, t; }" : "=r"(a) : "l"(p));
    return a;
}
static __device__ __forceinline__ void ldsm4(uint32_t& r0, uint32_t& r1, uint32_t& r2, uint32_t& r3,
                                             uint32_t a) {
    asm volatile("ldmatrix.sync.aligned.m8n8.x4.shared.b16 {%0,%1,%2,%3}, [%4];"
                 : "=r"(r0), "=r"(r1), "=r"(r2), "=r"(r3) : "r"(a));
}
static __device__ __forceinline__ void ldsm4t(uint32_t& r0, uint32_t& r1, uint32_t& r2, uint32_t& r3,
                                              uint32_t a) {
    asm volatile("ldmatrix.sync.aligned.m8n8.x4.trans.shared.b16 {%0,%1,%2,%3}, [%4];"
                 : "=r"(r0), "=r"(r1), "=r"(r2), "=r"(r3) : "r"(a));
}
static __device__ __forceinline__ void mma_f16(float4& d,
                                               uint32_t a0, uint32_t a1, uint32_t a2, uint32_t a3,
                                               uint32_t b0, uint32_t b1) {
    asm volatile("mma.sync.aligned.m16n8k16.row.col.f32.f16.f16.f32 "
                 "{%0,%1,%2,%3},{%4,%5,%6,%7},{%8,%9},{%0,%1,%2,%3};"
                 : "+f"(d.x), "+f"(d.y), "+f"(d.z), "+f"(d.w)
                 : "r"(a0), "r"(a1), "r"(a2), "r"(a3), "r"(b0), "r"(b1));
}
static __device__ __forceinline__ uint32_t pack2h(float f0, float f1) {
    __half2 h = __floats2half2_rn(f0, f1);
    return *(uint32_t*)&h;
}
static __device__ __forceinline__ void split2(float f0, float f1, uint32_t& hi, uint32_t& lo) {
    __half2 h = __floats2half2_rn(f0, f1);
    float2 hf = __half22float2(h);
    __half2 l = __floats2half2_rn(f0 - hf.x, f1 - hf.y);
    hi = *(uint32_t*)&h;
    lo = *(uint32_t*)&l;
}
static __device__ __forceinline__ float ldh(const char* smc, int idx) {
    return __half2float(*(const __half*)(smc + OFF_AH + idx * 2));
}

// 2-pass GEMM (GEMM1): A fp16, B fp16 hi+lo; acc += Ah*(Bl+Bh)
static __device__ __forceinline__ void gemm128(uint32_t aH, uint32_t bH, uint32_t bL,
                                               float4 (&acc)[2][8],
                                               int wm, int wn, int lane)
{
    const int arow = 32 * wm + (lane & 7) + 8 * ((lane >> 3) & 1);
    const int acol = 8 * (lane >> 4);
    const int bkl  = lane & 15;
    const int bnl  = 64 * wn + 8 * (lane >> 4);

    #pragma unroll 1
    for (int kb = 0; kb < 8; kb++) {
        uint32_t Ah[2][4];
        #pragma unroll
        for (int mi = 0; mi < 2; mi++) {
            uint32_t offA = (uint32_t)((arow + 16 * mi) * STRE + 16 * kb + acol) * 2;
            ldsm4(Ah[mi][0], Ah[mi][1], Ah[mi][2], Ah[mi][3], aH + offA);
        }
        #pragma unroll
        for (int j = 0; j < 4; j++) {
            uint32_t offB = (uint32_t)((16 * kb + bkl) * STRE + bnl + 16 * j) * 2;
            uint32_t bh0, bh1, bh2, bh3, bl0, bl1, bl2, bl3;
            ldsm4t(bh0, bh1, bh2, bh3, bH + offB);
            ldsm4t(bl0, bl1, bl2, bl3, bL + offB);
            #pragma unroll
            for (int mi = 0; mi < 2; mi++) {
                mma_f16(acc[mi][2*j],   Ah[mi][0], Ah[mi][1], Ah[mi][2], Ah[mi][3], bl0, bl1);
                mma_f16(acc[mi][2*j],   Ah[mi][0], Ah[mi][1], Ah[mi][2], Ah[mi][3], bh0, bh1);
                mma_f16(acc[mi][2*j+1], Ah[mi][0], Ah[mi][1], Ah[mi][2], Ah[mi][3], bl2, bl3);
                mma_f16(acc[mi][2*j+1], Ah[mi][0], Ah[mi][1], Ah[mi][2], Ah[mi][3], bh2, bh3);
            }
        }
    }
}

// 1-pass GEMM (GEMM2): A fp16, B hi only
static __device__ __forceinline__ void gemm128_hi(uint32_t aH, uint32_t bH,
                                                  float4 (&acc)[2][8],
                                                  int wm, int wn, int lane)
{
    const int arow = 32 * wm + (lane & 7) + 8 * ((lane >> 3) & 1);
    const int acol = 8 * (lane >> 4);
    const int bkl  = lane & 15;
    const int bnl  = 64 * wn + 8 * (lane >> 4);

    #pragma unroll 1
    for (int kb = 0; kb < 8; kb++) {
        uint32_t Ah[2][4];
        #pragma unroll
        for (int mi = 0; mi < 2; mi++) {
            uint32_t offA = (uint32_t)((arow + 16 * mi) * STRE + 16 * kb + acol) * 2;
            ldsm4(Ah[mi][0], Ah[mi][1], Ah[mi][2], Ah[mi][3], aH + offA);
        }
        #pragma unroll
        for (int j = 0; j < 4; j++) {
            uint32_t offB = (uint32_t)((16 * kb + bkl) * STRE + bnl + 16 * j) * 2;
            uint32_t bh0, bh1, bh2, bh3;
            ldsm4t(bh0, bh1, bh2, bh3, bH + offB);
            #pragma unroll
            for (int mi = 0; mi < 2; mi++) {
                mma_f16(acc[mi][2*j],   Ah[mi][0], Ah[mi][1], Ah[mi][2], Ah[mi][3], bh0, bh1);
                mma_f16(acc[mi][2*j+1], Ah[mi][0], Ah[mi][1], Ah[mi][2], Ah[mi][3], bh2, bh3);
            }
        }
    }
}

__global__ void __launch_bounds__(256, 2)
gcn_kernel(const float* __restrict__ x,
           const int*   __restrict__ ei,
           const float* __restrict__ ew,
           const float* __restrict__ W1, const float* __restrict__ b1,
           const float* __restrict__ W2, const float* __restrict__ b2,
           const float* __restrict__ b7, float* __restrict__ out)
{
    extern __shared__ char smc[];
    float* sMax  = (float*)(smc + OFF_MAX);
    float* sDinv = (float*)(smc + OFF_DINV);
    float* sBias = (float*)(smc + OFF_BIAS);

    const int g    = blockIdx.x >> 1;
    const int v    = blockIdx.x & 1;
    const int tid  = threadIdx.x;
    const int wid  = tid >> 5;
    const int lane = tid & 31;
    const int wm   = wid & 3;
    const int wn   = wid >> 2;

    const float* W   = v ? W2 : W1;
    const float* bbp = v ? b2 : b1;
    const float4 z4  = make_float4(0.f, 0.f, 0.f, 0.f);

    if (tid == 0 && v == 0) out[g] = b7[0];

    // ---- Phase 0: zero A pads + B pads; bias ----
    for (int i = tid; i < 116 * 6; i += 256) {
        int r = i / 6, cp = 58 + (i % 6);
        *(uint32_t*)(smc + OFF_AH + (uint32_t)(r * STRE + 2 * cp) * 2) = 0u;
    }
    for (int i = tid; i < 12 * 64; i += 256) {
        int r = 116 + (i >> 6), cp = i & 63;
        *(uint32_t*)(smc + OFF_AH + (uint32_t)(r * STRE + 2 * cp) * 2) = 0u;
    }
    for (int i = tid; i < 13 * 64; i += 256) {
        int r = 115 + (i >> 6), cp = i & 63;
        uint32_t off = (uint32_t)(r * STRE + 2 * cp) * 2;
        *(uint32_t*)(smc + OFF_BH + off) = 0u;
        *(uint32_t*)(smc + OFF_BL + off) = 0u;
    }
    if (tid < 128) sBias[tid] = bbp[tid];

    // ---- Phase 1: stage X -> A fp16, W -> B hi/lo ----
    {
        const float* xg = x + (size_t)(g * (2 * NODES) + v * NODES) * FEAT;
        for (int i = tid; i < NODES * 58; i += 256) {
            int r = i / 58, c2 = i - r * 58;
            float f0 = xg[r * FEAT + 2 * c2];
            float f1 = (c2 < 57) ? xg[r * FEAT + 2 * c2 + 1] : 0.f;
            *(uint32_t*)(smc + OFF_AH + (uint32_t)(r * STRE + 2 * c2) * 2) = pack2h(f0, f1);
        }
        for (int i = tid; i < (FEAT * HID) / 4; i += 256) {
            int r = i >> 5, c4 = i & 31;
            float4 w = ((const float4*)W)[i];
            uint32_t hi0, lo0, hi1, lo1;
            split2(w.x, w.y, hi0, lo0);
            split2(w.z, w.w, hi1, lo1);
            uint32_t off = (uint32_t)(r * STRE + 4 * c4) * 2;
            *(uint32_t*)(smc + OFF_BH + off)     = hi0;
            *(uint32_t*)(smc + OFF_BH + off + 4) = hi1;
            *(uint32_t*)(smc + OFF_BL + off)     = lo0;
            *(uint32_t*)(smc + OFF_BL + off + 4) = lo1;
        }
    }
    __syncthreads();

    const uint32_t sb = smem_u32(smc);
    const uint32_t aH = sb + OFF_AH;
    const uint32_t bH = sb + OFF_BH, bL = sb + OFF_BL;
    const int gr = lane >> 2;
    const int t2 = (lane & 3) * 2;

    // ---- Phase 2: GEMM1  H = X @ W (acc stays in registers) ----
    float4 acc[2][8];
    #pragma unroll
    for (int mi = 0; mi < 2; mi++)
        #pragma unroll
        for (int nt = 0; nt < 8; nt++) acc[mi][nt] = z4;
    gemm128(aH, bH, bL, acc, wm, wn, lane);
    __syncthreads();

    // ---- Phase 3: zero full A ----
    for (int i = tid; i < 34816 / 16; i += 256) ((float4*)(smc + OFF_AH))[i] = z4;
    __syncthreads();

    // ---- Phase 4: scatter edges into A as fp16 half2 atomics ----
    {
        const int ebase = g * SEG2 + v * LENN;
        const int eoff  = g * (2 * NODES) + v * NODES;
        const int*   eis = ei + ebase;
        const int*   eid = ei + (NB * SEG2) + ebase;
        const float* ewp = ew + ebase;
        for (int e0 = tid; e0 < 6144; e0 += 2048) {
            int sE[8], dE[8]; float wE[8];
            #pragma unroll
            for (int j = 0; j < 8; j++) sE[j] = eis[e0 + 256 * j];
            #pragma unroll
            for (int j = 0; j < 8; j++) dE[j] = eid[e0 + 256 * j];
            #pragma unroll
            for (int j = 0; j < 8; j++) wE[j] = ewp[e0 + 256 * j];
            #pragma unroll
            for (int j = 0; j < 8; j++) {
                int off = (dE[j] - eoff) * STRE + (sE[j] - eoff);
                __half wh = __float2half(wE[j]);
                __half2 val = (off & 1) ? __halves2half2(__float2half(0.f), wh)
                                        : __halves2half2(wh, __float2half(0.f));
                atomicAdd((__half2*)(smc + OFF_AH + (uint32_t)(off & ~1) * 2), val);
            }
        }
        for (int e = 6144 + tid; e < LENN; e += 256) {
            int off = (eid[e] - eoff) * STRE + (eis[e] - eoff);
            __half wh = __float2half(ewp[e]);
            __half2 val = (off & 1) ? __halves2half2(__float2half(0.f), wh)
                                    : __halves2half2(wh, __float2half(0.f));
            atomicAdd((__half2*)(smc + OFF_AH + (uint32_t)(off & ~1) * 2), val);
        }
    }
    __syncthreads();

    // ---- Phase 5: dinv[r] = rsqrt(rowsum(A[r]) + 1); add self-loop diag ----
    for (int r = wid; r < 128; r += 8) {
        float dv = 1.0f;
        if (r < NODES) {
            float s = ldh(smc, r * STRE + lane)
                    + ldh(smc, r * STRE + 32 + lane)
                    + ldh(smc, r * STRE + 64 + lane)
                    + ldh(smc, r * STRE + 96 + lane);
            #pragma unroll
            for (int o = 16; o; o >>= 1) s += __shfl_xor_sync(0xffffffffu, s, o);
            dv = rsqrtf(s + 1.0f);
            if (lane == 0) {
                __half* dp = (__half*)(smc + OFF_AH + (uint32_t)(r * STRE + r) * 2);
                *dp = __float2half(__half2float(*dp) + 1.0f);
            }
        }
        if (lane == 0) sDinv[r] = dv;
    }
    __syncthreads();

    // ---- Phase 6: H' = dinv*H -> B hi only (GEMM2 is single-pass) ----
    #pragma unroll
    for (int mi = 0; mi < 2; mi++) {
        int r0 = 32 * wm + 16 * mi + gr;
        int r1 = r0 + 8;
        float dv0 = sDinv[r0], dv1 = sDinv[r1];
        #pragma unroll
        for (int nt = 0; nt < 8; nt++) {
            int c0 = 64 * wn + 8 * nt + t2;
            float4 a = acc[mi][nt];
            *(uint32_t*)(smc + OFF_BH + (uint32_t)(r0 * STRE + c0) * 2) = pack2h(a.x * dv0, a.y * dv0);
            *(uint32_t*)(smc + OFF_BH + (uint32_t)(r1 * STRE + c0) * 2) = pack2h(a.z * dv1, a.w * dv1);
        }
    }
    __syncthreads();

    // ---- Phase 7: GEMM2  out = (S0+I) @ H' (hi-only); epilogue + channel-max ----
    #pragma unroll
    for (int mi = 0; mi < 2; mi++)
        #pragma unroll
        for (int nt = 0; nt < 8; nt++) acc[mi][nt] = z4;
    gemm128_hi(aH, bH, acc, wm, wn, lane);

    #pragma unroll
    for (int mi = 0; mi < 2; mi++) {
        int r0 = 32 * wm + 16 * mi + gr;
        int r1 = r0 + 8;
        float dv0 = sDinv[r0], dv1 = sDinv[r1];
        float m0 = -3.0e38f, m1 = -3.0e38f;
        #pragma unroll
        for (int nt = 0; nt < 8; nt++) {
            int c0 = 64 * wn + 8 * nt + t2;
            float b0 = sBias[c0], b1 = sBias[c0 + 1];
            float4 a = acc[mi][nt];
            m0 = fmaxf(m0, fmaxf(fmaf(dv0, a.x, b0), fmaf(dv0, a.y, b1)));
            m1 = fmaxf(m1, fmaxf(fmaf(dv1, a.z, b0), fmaf(dv1, a.w, b1)));
        }
        m0 = fmaxf(m0, __shfl_xor_sync(0xffffffffu, m0, 1));
        m0 = fmaxf(m0, __shfl_xor_sync(0xffffffffu, m0, 2));
        m1 = fmaxf(m1, __shfl_xor_sync(0xffffffffu, m1, 1));
        m1 = fmaxf(m1, __shfl_xor_sync(0xffffffffu, m1, 2));
        if ((lane & 3) == 0) {
            sMax[2 * r0 + wn] = m0;
            sMax[2 * r1 + wn] = m1;
        }
    }
    __syncthreads();
    for (int r = tid; r < NODES; r += 256)
        g_featT[(2 * r + v) * NB + g] = fmaxf(sMax[2 * r], sMax[2 * r + 1]);
}

// ---- MLP v7: 512 CTAs = 128 col-groups x 4 graph-splits; 256 threads.
// CTA (cg, gs): cols 4cg..4cg+3, graphs 64gs..64gs+63.
#define FMA16(F, Wv)                                                 \
    a0.x = fmaf(F.x, Wv.x, a0.x); a0.y = fmaf(F.x, Wv.y, a0.y);      \
    a0.z = fmaf(F.x, Wv.z, a0.z); a0.w = fmaf(F.x, Wv.w, a0.w);      \
    a1.x = fmaf(F.y, Wv.x, a1.x); a1.y = fmaf(F.y, Wv.y, a1.y);      \
    a1.z = fmaf(F.y, Wv.z, a1.z); a1.w = fmaf(F.y, Wv.w, a1.w);      \
    a2.x = fmaf(F.z, Wv.x, a2.x); a2.y = fmaf(F.z, Wv.y, a2.y);      \
    a2.z = fmaf(F.z, Wv.z, a2.z); a2.w = fmaf(F.z, Wv.w, a2.w);      \
    a3.x = fmaf(F.w, Wv.x, a3.x); a3.y = fmaf(F.w, Wv.y, a3.y);      \
    a3.z = fmaf(F.w, Wv.z, a3.z); a3.w = fmaf(F.w, Wv.w, a3.w);

__global__ void __launch_bounds__(256, 4)
mlp_kernel(const float* __restrict__ W6, const float* __restrict__ b6,
           const float* __restrict__ W7, float* __restrict__ out)
{
    __shared__ float4 sW[232];          // W6[k][c0..c0+3]
    __shared__ float4 sP[16][16][4];    // [k-slice][graph-quad][graph-in-quad]
    const int tid = threadIdx.x;
    const int cg  = blockIdx.x >> 2;
    const int gs  = blockIdx.x & 3;
    const int c0  = cg * 4;
    const int ks  = tid >> 4;           // k-slice 0..15
    const int gq  = tid & 15;           // graph quad within the 64-graph split

    if (tid < 232) sW[tid] = *(const float4*)(W6 + tid * HC + c0);
    __syncthreads();

    float4 a0 = make_float4(0.f,0.f,0.f,0.f);
    float4 a1 = a0, a2 = a0, a3 = a0;
    const float4* fp = (const float4*)(g_featT) + gs * 16 + gq;
    const int len   = (ks < 8) ? 15 : 14;
    const int kbase = (ks < 8) ? 15 * ks : 120 + 14 * (ks - 8);
    int kk = 0;
    #pragma unroll 1
    for (; kk + 4 <= len; kk += 4) {
        int k0 = kbase + kk;
        float4 f0 = fp[(k0 + 0) * 64];
        float4 f1 = fp[(k0 + 1) * 64];
        float4 f2 = fp[(k0 + 2) * 64];
        float4 f3 = fp[(k0 + 3) * 64];
        float4 w0 = sW[k0 + 0];
        float4 w1 = sW[k0 + 1];
        float4 w2 = sW[k0 + 2];
        float4 w3 = sW[k0 + 3];
        FMA16(f0, w0)
        FMA16(f1, w1)
        FMA16(f2, w2)
        FMA16(f3, w3)
    }
    {   // tail (2 or 3)
        int k0 = kbase + kk;
        float4 f0 = fp[(k0 + 0) * 64];
        float4 f1 = fp[(k0 + 1) * 64];
        float4 w0 = sW[k0 + 0];
        float4 w1 = sW[k0 + 1];
        FMA16(f0, w0)
        FMA16(f1, w1)
        if (kk + 3 <= len) {
            float4 f2 = fp[(k0 + 2) * 64];
            float4 w2 = sW[k0 + 2];
            FMA16(f2, w2)
        }
    }
    sP[ks][gq][0] = a0;
    sP[ks][gq][1] = a1;
    sP[ks][gq][2] = a2;
    sP[ks][gq][3] = a3;
    __syncthreads();

    if (tid < 64) {
        const int gq2 = tid >> 2;
        const int gi  = tid & 3;
        float4 s = sP[0][gq2][gi];
        #pragma unroll
        for (int k = 1; k < 16; k++) {
            float4 t = sP[k][gq2][gi];
            s.x += t.x; s.y += t.y; s.z += t.z; s.w += t.w;
        }
        float4 bv = *(const float4*)(b6 + c0);
        float4 wv = *(const float4*)(W7 + c0);
        float h0 = fmaxf(s.x + bv.x, 0.f);
        float h1 = fmaxf(s.y + bv.y, 0.f);
        float h2 = fmaxf(s.z + bv.z, 0.f);
        float h3 = fmaxf(s.w + bv.w, 0.f);
        float p = fmaf(h0, wv.x, fmaf(h1, wv.y, fmaf(h2, wv.z, h3 * wv.w)));
        atomicAdd(&out[gs * 64 + tid], p);
    }
}

extern "C" void kernel_launch(void* const* d_in, const int* in_sizes, int n_in,
                              void* d_out, int out_size)
{
    const float* x  = (const float*)d_in[0];
    const int*   ei = (const int*)  d_in[1];
    const float* ew = (const float*)d_in[2];
    // d_in[3] = batch (unused)
    const float* W1 = (const float*)d_in[4];
    const float* b1 = (const float*)d_in[5];
    const float* W2 = (const float*)d_in[6];
    const float* b2 = (const float*)d_in[7];
    const float* W6 = (const float*)d_in[8];
    const float* b6 = (const float*)d_in[9];
    const float* W7 = (const float*)d_in[10];
    const float* b7 = (const float*)d_in[11];

    cudaFuncSetAttribute(gcn_kernel, cudaFuncAttributeMaxDynamicSharedMemorySize, SMEM_BYTES);

    gcn_kernel<<<2 * NB, 256, SMEM_BYTES>>>(x, ei, ew, W1, b1, W2, b2, b7, (float*)d_out);
    mlp_kernel<<<4 * HC / 4, 256>>>(W6, b6, W7, (float*)d_out);
}

// round 16
// speedup vs baseline: 2.3401x; 1.0006x over previous
#include <cuda_runtime.h>
#include <cuda_fp16.h>
#include <cstdint>

#define NB     256
#define NODES  116
#define FEAT   115
#define HID    128
#define LENN   6670
#define SEG2   13456
#define HC     512
#define STRE   136         // fp16 matrix row stride (elements)

// smem byte offsets (no B-lo buffer; 71.7KB -> occ 2 with big slack)
#define OFF_AH   0                 // A fp16 [128][136] (X, then scatter target S0+I)
#define OFF_BH   34816             // B fp16 [128][136] (W, later H') — K-MAJOR [k][n]
#define OFF_MAX  69632             // float [128][2]
#define OFF_DINV 70656             // 128 floats
#define OFF_BIAS 71168             // 128 floats
#define SMEM_BYTES 71680

__device__ float g_featT[232 * NB];     // TRANSPOSED: featT[k][g]
__device__ uint4 g_Wh[2][1840];         // W1/W2 as fp16, [115][128] halves (16 uint4/row)

static __device__ __forceinline__ uint32_t smem_u32(const void* p) {
    uint32_t a;
    asm("{ .reg .u64 t; cvta.to.shared.u64 t, %1; cvt.u32.u64 %0, t; }" : "=r"(a) : "l"(p));
    return a;
}
static __device__ __forceinline__ void ldsm4(uint32_t& r0, uint32_t& r1, uint32_t& r2, uint32_t& r3,
                                             uint32_t a) {
    asm volatile("ldmatrix.sync.aligned.m8n8.x4.shared.b16 {%0,%1,%2,%3}, [%4];"
                 : "=r"(r0), "=r"(r1), "=r"(r2), "=r"(r3) : "r"(a));
}
static __device__ __forceinline__ void ldsm4t(uint32_t& r0, uint32_t& r1, uint32_t& r2, uint32_t& r3,
                                              uint32_t a) {
    asm volatile("ldmatrix.sync.aligned.m8n8.x4.trans.shared.b16 {%0,%1,%2,%3}, [%4];"
                 : "=r"(r0), "=r"(r1), "=r"(r2), "=r"(r3) : "r"(a));
}
static __device__ __forceinline__ void mma_f16(float4& d,
                                               uint32_t a0, uint32_t a1, uint32_t a2, uint32_t a3,
                                               uint32_t b0, uint32_t b1) {
    asm volatile("mma.sync.aligned.m16n8k16.row.col.f32.f16.f16.f32 "
                 "{%0,%1,%2,%3},{%4,%5,%6,%7},{%8,%9},{%0,%1,%2,%3};"
                 : "+f"(d.x), "+f"(d.y), "+f"(d.z), "+f"(d.w)
                 : "r"(a0), "r"(a1), "r"(a2), "r"(a3), "r"(b0), "r"(b1));
}
static __device__ __forceinline__ uint32_t pack2h(float f0, float f1) {
    __half2 h = __floats2half2_rn(f0, f1);
    return *(uint32_t*)&h;
}
static __device__ __forceinline__ float ldh(const char* smc, int idx) {
    return __half2float(*(const __half*)(smc + OFF_AH + idx * 2));
}

// 1-pass fp16 GEMM: A fp16, B fp16 (hi only), fp32 accum
static __device__ __forceinline__ void gemm128_hi(uint32_t aH, uint32_t bH,
                                                  float4 (&acc)[2][8],
                                                  int wm, int wn, int lane)
{
    const int arow = 32 * wm + (lane & 7) + 8 * ((lane >> 3) & 1);
    const int acol = 8 * (lane >> 4);
    const int bkl  = lane & 15;
    const int bnl  = 64 * wn + 8 * (lane >> 4);

    #pragma unroll 1
    for (int kb = 0; kb < 8; kb++) {
        uint32_t Ah[2][4];
        #pragma unroll
        for (int mi = 0; mi < 2; mi++) {
            uint32_t offA = (uint32_t)((arow + 16 * mi) * STRE + 16 * kb + acol) * 2;
            ldsm4(Ah[mi][0], Ah[mi][1], Ah[mi][2], Ah[mi][3], aH + offA);
        }
        #pragma unroll
        for (int j = 0; j < 4; j++) {
            uint32_t offB = (uint32_t)((16 * kb + bkl) * STRE + bnl + 16 * j) * 2;
            uint32_t bh0, bh1, bh2, bh3;
            ldsm4t(bh0, bh1, bh2, bh3, bH + offB);
            #pragma unroll
            for (int mi = 0; mi < 2; mi++) {
                mma_f16(acc[mi][2*j],   Ah[mi][0], Ah[mi][1], Ah[mi][2], Ah[mi][3], bh0, bh1);
                mma_f16(acc[mi][2*j+1], Ah[mi][0], Ah[mi][1], Ah[mi][2], Ah[mi][3], bh2, bh3);
            }
        }
    }
}

// ---- prep: convert W1/W2 to fp16 once (14720 uint32 total) ----
__global__ void prep_kernel(const float* __restrict__ W1, const float* __restrict__ W2)
{
    int idx = blockIdx.x * 256 + threadIdx.x;     // half2 index
    const int NW = FEAT * HID / 2;                // 7360 per matrix
    if (idx < NW) {
        float2 f = ((const float2*)W1)[idx];
        ((uint32_t*)g_Wh[0])[idx] = pack2h(f.x, f.y);
    } else if (idx < 2 * NW) {
        int j = idx - NW;
        float2 f = ((const float2*)W2)[j];
        ((uint32_t*)g_Wh[1])[idx - NW] = pack2h(f.x, f.y);
    }
}

__global__ void __launch_bounds__(256, 2)
gcn_kernel(const float* __restrict__ x,
           const int*   __restrict__ ei,
           const float* __restrict__ ew,
           const float* __restrict__ b1, const float* __restrict__ b2,
           const float* __restrict__ b7, float* __restrict__ out)
{
    extern __shared__ char smc[];
    float* sMax  = (float*)(smc + OFF_MAX);
    float* sDinv = (float*)(smc + OFF_DINV);
    float* sBias = (float*)(smc + OFF_BIAS);

    const int g    = blockIdx.x >> 1;
    const int v    = blockIdx.x & 1;
    const int tid  = threadIdx.x;
    const int wid  = tid >> 5;
    const int lane = tid & 31;
    const int wm   = wid & 3;
    const int wn   = wid >> 2;

    const float* bbp = v ? b2 : b1;
    const float4 z4  = make_float4(0.f, 0.f, 0.f, 0.f);

    if (tid == 0 && v == 0) out[g] = b7[0];

    // ---- Phase 0: zero A pads + B pads; bias ----
    for (int i = tid; i < 116 * 6; i += 256) {           // A cols 116-127, rows 0-115
        int r = i / 6, cp = 58 + (i % 6);
        *(uint32_t*)(smc + OFF_AH + (uint32_t)(r * STRE + 2 * cp) * 2) = 0u;
    }
    for (int i = tid; i < 12 * 64; i += 256) {           // A rows 116-127
        int r = 116 + (i >> 6), cp = i & 63;
        *(uint32_t*)(smc + OFF_AH + (uint32_t)(r * STRE + 2 * cp) * 2) = 0u;
    }
    for (int i = tid; i < 13 * 64; i += 256) {           // B rows 115-127
        int r = 115 + (i >> 6), cp = i & 63;
        *(uint32_t*)(smc + OFF_BH + (uint32_t)(r * STRE + 2 * cp) * 2) = 0u;
    }
    if (tid < 128) sBias[tid] = bbp[tid];

    // ---- Phase 1: stage X -> A fp16 (div-free); W <- g_Wh (uint4 copy) ----
    {
        const float* xg = x + (size_t)(g * (2 * NODES) + v * NODES) * FEAT;
        const int c2 = tid & 63;          // column pair
        const int r0 = tid >> 6;          // row phase 0..3
        if (c2 < 58) {
            const float* xp = xg + r0 * FEAT + 2 * c2;
            uint32_t dst = (uint32_t)(r0 * STRE + 2 * c2) * 2;
            const bool full = (c2 < 57);
            #pragma unroll 1
            for (int r = r0; r < NODES; r += 4) {
                float f0 = xp[0];
                float f1 = full ? xp[1] : 0.f;
                *(uint32_t*)(smc + OFF_AH + dst) = pack2h(f0, f1);
                xp  += 4 * FEAT;
                dst += 4 * STRE * 2;
            }
        }
        // W: 115 rows x 16 uint4
        const uint4* Wp = g_Wh[v];
        const int q  = tid & 15;
        const int rw = tid >> 4;          // row phase 0..15
        uint32_t dstW = (uint32_t)(rw * STRE + q * 8) * 2;
        #pragma unroll 1
        for (int r = rw; r < FEAT; r += 16) {
            uint4 w = Wp[r * 16 + q];
            *(uint4*)(smc + OFF_BH + dstW) = w;
            dstW += 16 * STRE * 2;
        }
    }
    __syncthreads();

    const uint32_t sb = smem_u32(smc);
    const uint32_t aH = sb + OFF_AH;
    const uint32_t bH = sb + OFF_BH;
    const int gr = lane >> 2;
    const int t2 = (lane & 3) * 2;

    // ---- Phase 2: GEMM1  H = X @ W (hi-only; acc stays in registers) ----
    float4 acc[2][8];
    #pragma unroll
    for (int mi = 0; mi < 2; mi++)
        #pragma unroll
        for (int nt = 0; nt < 8; nt++) acc[mi][nt] = z4;
    gemm128_hi(aH, bH, acc, wm, wn, lane);
    __syncthreads();

    // ---- Phase 3: zero full A ----
    for (int i = tid; i < 34816 / 16; i += 256) ((float4*)(smc + OFF_AH))[i] = z4;
    __syncthreads();

    // ---- Phase 4: scatter edges into A as fp16 half2 atomics ----
    {
        const int ebase = g * SEG2 + v * LENN;
        const int eoff  = g * (2 * NODES) + v * NODES;
        const int*   eis = ei + ebase;
        const int*   eid = ei + (NB * SEG2) + ebase;
        const float* ewp = ew + ebase;
        for (int e0 = tid; e0 < 6144; e0 += 2048) {
            int sE[8], dE[8]; float wE[8];
            #pragma unroll
            for (int j = 0; j < 8; j++) sE[j] = eis[e0 + 256 * j];
            #pragma unroll
            for (int j = 0; j < 8; j++) dE[j] = eid[e0 + 256 * j];
            #pragma unroll
            for (int j = 0; j < 8; j++) wE[j] = ewp[e0 + 256 * j];
            #pragma unroll
            for (int j = 0; j < 8; j++) {
                int off = (dE[j] - eoff) * STRE + (sE[j] - eoff);
                __half wh = __float2half(wE[j]);
                __half2 val = (off & 1) ? __halves2half2(__float2half(0.f), wh)
                                        : __halves2half2(wh, __float2half(0.f));
                atomicAdd((__half2*)(smc + OFF_AH + (uint32_t)(off & ~1) * 2), val);
            }
        }
        for (int e = 6144 + tid; e < LENN; e += 256) {
            int off = (eid[e] - eoff) * STRE + (eis[e] - eoff);
            __half wh = __float2half(ewp[e]);
            __half2 val = (off & 1) ? __halves2half2(__float2half(0.f), wh)
                                    : __halves2half2(wh, __float2half(0.f));
            atomicAdd((__half2*)(smc + OFF_AH + (uint32_t)(off & ~1) * 2), val);
        }
    }
    __syncthreads();

    // ---- Phase 5: dinv[r] = rsqrt(rowsum(A[r]) + 1); add self-loop diag ----
    for (int r = wid; r < 128; r += 8) {
        float dv = 1.0f;
        if (r < NODES) {
            float s = ldh(smc, r * STRE + lane)
                    + ldh(smc, r * STRE + 32 + lane)
                    + ldh(smc, r * STRE + 64 + lane)
                    + ldh(smc, r * STRE + 96 + lane);
            #pragma unroll
            for (int o = 16; o; o >>= 1) s += __shfl_xor_sync(0xffffffffu, s, o);
            dv = rsqrtf(s + 1.0f);
            if (lane == 0) {
                __half* dp = (__half*)(smc + OFF_AH + (uint32_t)(r * STRE + r) * 2);
                *dp = __float2half(__half2float(*dp) + 1.0f);
            }
        }
        if (lane == 0) sDinv[r] = dv;
    }
    __syncthreads();

    // ---- Phase 6: H' = dinv*H -> B (hi only) ----
    #pragma unroll
    for (int mi = 0; mi < 2; mi++) {
        int r0 = 32 * wm + 16 * mi + gr;
        int r1 = r0 + 8;
        float dv0 = sDinv[r0], dv1 = sDinv[r1];
        #pragma unroll
        for (int nt = 0; nt < 8; nt++) {
            int c0 = 64 * wn + 8 * nt + t2;
            float4 a = acc[mi][nt];
            *(uint32_t*)(smc + OFF_BH + (uint32_t)(r0 * STRE + c0) * 2) = pack2h(a.x * dv0, a.y * dv0);
            *(uint32_t*)(smc + OFF_BH + (uint32_t)(r1 * STRE + c0) * 2) = pack2h(a.z * dv1, a.w * dv1);
        }
    }
    __syncthreads();

    // ---- Phase 7: GEMM2  out = (S0+I) @ H'; epilogue + channel-max ----
    #pragma unroll
    for (int mi = 0; mi < 2; mi++)
        #pragma unroll
        for (int nt = 0; nt < 8; nt++) acc[mi][nt] = z4;
    gemm128_hi(aH, bH, acc, wm, wn, lane);

    #pragma unroll
    for (int mi = 0; mi < 2; mi++) {
        int r0 = 32 * wm + 16 * mi + gr;
        int r1 = r0 + 8;
        float dv0 = sDinv[r0], dv1 = sDinv[r1];
        float m0 = -3.0e38f, m1 = -3.0e38f;
        #pragma unroll
        for (int nt = 0; nt < 8; nt++) {
            int c0 = 64 * wn + 8 * nt + t2;
            float b0 = sBias[c0], b1 = sBias[c0 + 1];
            float4 a = acc[mi][nt];
            m0 = fmaxf(m0, fmaxf(fmaf(dv0, a.x, b0), fmaf(dv0, a.y, b1)));
            m1 = fmaxf(m1, fmaxf(fmaf(dv1, a.z, b0), fmaf(dv1, a.w, b1)));
        }
        m0 = fmaxf(m0, __shfl_xor_sync(0xffffffffu, m0, 1));
        m0 = fmaxf(m0, __shfl_xor_sync(0xffffffffu, m0, 2));
        m1 = fmaxf(m1, __shfl_xor_sync(0xffffffffu, m1, 1));
        m1 = fmaxf(m1, __shfl_xor_sync(0xffffffffu, m1, 2));
        if ((lane & 3) == 0) {
            sMax[2 * r0 + wn] = m0;
            sMax[2 * r1 + wn] = m1;
        }
    }
    __syncthreads();
    for (int r = tid; r < NODES; r += 256)
        g_featT[(2 * r + v) * NB + g] = fmaxf(sMax[2 * r], sMax[2 * r + 1]);
}

// ---- MLP (R15 version): 512 CTAs = 128 col-groups x 4 graph-splits ----
#define FMA16(F, Wv)                                                 \
    a0.x = fmaf(F.x, Wv.x, a0.x); a0.y = fmaf(F.x, Wv.y, a0.y);      \
    a0.z = fmaf(F.x, Wv.z, a0.z); a0.w = fmaf(F.x, Wv.w, a0.w);      \
    a1.x = fmaf(F.y, Wv.x, a1.x); a1.y = fmaf(F.y, Wv.y, a1.y);      \
    a1.z = fmaf(F.y, Wv.z, a1.z); a1.w = fmaf(F.y, Wv.w, a1.w);      \
    a2.x = fmaf(F.z, Wv.x, a2.x); a2.y = fmaf(F.z, Wv.y, a2.y);      \
    a2.z = fmaf(F.z, Wv.z, a2.z); a2.w = fmaf(F.z, Wv.w, a2.w);      \
    a3.x = fmaf(F.w, Wv.x, a3.x); a3.y = fmaf(F.w, Wv.y, a3.y);      \
    a3.z = fmaf(F.w, Wv.z, a3.z); a3.w = fmaf(F.w, Wv.w, a3.w);

__global__ void __launch_bounds__(256, 4)
mlp_kernel(const float* __restrict__ W6, const float* __restrict__ b6,
           const float* __restrict__ W7, float* __restrict__ out)
{
    __shared__ float4 sW[232];
    __shared__ float4 sP[16][16][4];
    const int tid = threadIdx.x;
    const int cg  = blockIdx.x >> 2;
    const int gs  = blockIdx.x & 3;
    const int c0  = cg * 4;
    const int ks  = tid >> 4;
    const int gq  = tid & 15;

    if (tid < 232) sW[tid] = *(const float4*)(W6 + tid * HC + c0);
    __syncthreads();

    float4 a0 = make_float4(0.f,0.f,0.f,0.f);
    float4 a1 = a0, a2 = a0, a3 = a0;
    const float4* fp = (const float4*)(g_featT) + gs * 16 + gq;
    const int len   = (ks < 8) ? 15 : 14;
    const int kbase = (ks < 8) ? 15 * ks : 120 + 14 * (ks - 8);
    int kk = 0;
    #pragma unroll 1
    for (; kk + 4 <= len; kk += 4) {
        int k0 = kbase + kk;
        float4 f0 = fp[(k0 + 0) * 64];
        float4 f1 = fp[(k0 + 1) * 64];
        float4 f2 = fp[(k0 + 2) * 64];
        float4 f3 = fp[(k0 + 3) * 64];
        float4 w0 = sW[k0 + 0];
        float4 w1 = sW[k0 + 1];
        float4 w2 = sW[k0 + 2];
        float4 w3 = sW[k0 + 3];
        FMA16(f0, w0)
        FMA16(f1, w1)
        FMA16(f2, w2)
        FMA16(f3, w3)
    }
    {
        int k0 = kbase + kk;
        float4 f0 = fp[(k0 + 0) * 64];
        float4 f1 = fp[(k0 + 1) * 64];
        float4 w0 = sW[k0 + 0];
        float4 w1 = sW[k0 + 1];
        FMA16(f0, w0)
        FMA16(f1, w1)
        if (kk + 3 <= len) {
            float4 f2 = fp[(k0 + 2) * 64];
            float4 w2 = sW[k0 + 2];
            FMA16(f2, w2)
        }
    }
    sP[ks][gq][0] = a0;
    sP[ks][gq][1] = a1;
    sP[ks][gq][2] = a2;
    sP[ks][gq][3] = a3;
    __syncthreads();

    if (tid < 64) {
        const int gq2 = tid >> 2;
        const int gi  = tid & 3;
        float4 s = sP[0][gq2][gi];
        #pragma unroll
        for (int k = 1; k < 16; k++) {
            float4 t = sP[k][gq2][gi];
            s.x += t.x; s.y += t.y; s.z += t.z; s.w += t.w;
        }
        float4 bv = *(const float4*)(b6 + c0);
        float4 wv = *(const float4*)(W7 + c0);
        float h0 = fmaxf(s.x + bv.x, 0.f);
        float h1 = fmaxf(s.y + bv.y, 0.f);
        float h2 = fmaxf(s.z + bv.z, 0.f);
        float h3 = fmaxf(s.w + bv.w, 0.f);
        float p = fmaf(h0, wv.x, fmaf(h1, wv.y, fmaf(h2, wv.z, h3 * wv.w)));
        atomicAdd(&out[gs * 64 + tid], p);
    }
}

extern "C" void kernel_launch(void* const* d_in, const int* in_sizes, int n_in,
                              void* d_out, int out_size)
{
    const float* x  = (const float*)d_in[0];
    const int*   ei = (const int*)  d_in[1];
    const float* ew = (const float*)d_in[2];
    // d_in[3] = batch (unused)
    const float* W1 = (const float*)d_in[4];
    const float* b1 = (const float*)d_in[5];
    const float* W2 = (const float*)d_in[6];
    const float* b2 = (const float*)d_in[7];
    const float* W6 = (const float*)d_in[8];
    const float* b6 = (const float*)d_in[9];
    const float* W7 = (const float*)d_in[10];
    const float* b7 = (const float*)d_in[11];

    cudaFuncSetAttribute(gcn_kernel, cudaFuncAttributeMaxDynamicSharedMemorySize, SMEM_BYTES);

    prep_kernel<<<58, 256>>>(W1, W2);
    gcn_kernel<<<2 * NB, 256, SMEM_BYTES>>>(x, ei, ew, b1, b2, b7, (float*)d_out);
    mlp_kernel<<<4 * HC / 4, 256>>>(W6, b6, W7, (float*)d_out);
}